// round 1
// baseline (speedup 1.0000x reference)
#include <cuda_runtime.h>

#define Bn   4
#define Cn   256
#define Nn   4096
#define NHn  4
#define HDn  64

// Scratch (device globals; no runtime allocation allowed)
__device__ float g_tln[Bn * Nn * Cn];            // LN'd tokens [b][n][c]
__device__ float g_q[Bn * NHn * Nn * HDn];       // [bh][n][d]
__device__ float g_k[Bn * NHn * Nn * HDn];
__device__ float g_v[Bn * NHn * Nn * HDn];
__device__ float g_o[Bn * Nn * Cn];              // attention out [b][n][c]

// ---------------------------------------------------------------------------
// Kernel 1: LayerNorm over C with NCHW -> [B,N,C] transpose.
// Block: (32,8). One block handles 32 tokens. smem tile padded to stride 33
// so both the channel-major reduction reads and token-major final reads are
// bank-conflict free.
// ---------------------------------------------------------------------------
__global__ void ln_kernel(const float* __restrict__ x,
                          const float* __restrict__ gamma,
                          const float* __restrict__ beta) {
    __shared__ float sm[256 * 33];
    __shared__ float red[2][8][32];
    __shared__ float sMean[32], sRstd[32];

    int blk = blockIdx.x;
    int bb  = blk >> 7;            // / 128 tiles per batch
    int n0  = (blk & 127) * 32;
    int tx  = threadIdx.x;         // token within tile
    int ty  = threadIdx.y;

    const float* xb = x + (size_t)bb * Cn * Nn;
    for (int c = ty; c < 256; c += 8)
        sm[c * 33 + tx] = xb[(size_t)c * Nn + n0 + tx];
    __syncthreads();

    float s = 0.f, s2 = 0.f;
    for (int c = ty; c < 256; c += 8) {
        float v = sm[c * 33 + tx];
        s += v; s2 += v * v;
    }
    red[0][ty][tx] = s;
    red[1][ty][tx] = s2;
    __syncthreads();

    if (ty == 0) {
        float a = 0.f, b2 = 0.f;
        #pragma unroll
        for (int i = 0; i < 8; i++) { a += red[0][i][tx]; b2 += red[1][i][tx]; }
        float mean = a * (1.f / 256.f);
        float var  = b2 * (1.f / 256.f) - mean * mean;
        sMean[tx] = mean;
        sRstd[tx] = rsqrtf(var + 1e-5f);
    }
    __syncthreads();

    int c = ty * 32 + tx;          // channel handled by this thread
    float gc = gamma[c], bc = beta[c];
    float* out = g_tln + ((size_t)bb * Nn + n0) * Cn;
    #pragma unroll 8
    for (int t = 0; t < 32; t++) {
        float v = (sm[c * 33 + t] - sMean[t]) * sRstd[t] * gc + bc;
        out[(size_t)t * Cn + c] = v;
    }
}

// ---------------------------------------------------------------------------
// Kernel 2: QKV GEMM  [16384,256] @ [256,768], output scattered into
// g_q/g_k/g_v with [bh][n][d] layout. Block tile 64x64, BK=16, thread 4x4.
// Each block covers one (s,h) pair (since 64 | 256).
// ---------------------------------------------------------------------------
__global__ void qkv_kernel(const float* __restrict__ w) {
    __shared__ float As[16 * 65];    // A transposed: [k][m]
    __shared__ float Bs[16 * 64];    // [k][n]

    int s  = blockIdx.x >> 2;        // 0=q,1=k,2=v
    int h  = blockIdx.x & 3;
    int n0 = blockIdx.x * 64;        // global weight column base
    int m0 = blockIdx.y * 64;

    int tid = threadIdx.x;
    int tx = tid & 15, ty = tid >> 4;
    float acc[4][4] = {};

    const float* A = g_tln + (size_t)m0 * Cn;
    for (int k0 = 0; k0 < 256; k0 += 16) {
        #pragma unroll
        for (int l = 0; l < 4; l++) {
            int idx = tid + l * 256;
            int m = idx >> 4, k = idx & 15;
            As[k * 65 + m] = A[(size_t)m * Cn + k0 + k];
        }
        #pragma unroll
        for (int l = 0; l < 4; l++) {
            int idx = tid + l * 256;
            int k = idx >> 6, n = idx & 63;
            Bs[k * 64 + n] = w[(size_t)(k0 + k) * 768 + n0 + n];
        }
        __syncthreads();
        #pragma unroll
        for (int k = 0; k < 16; k++) {
            float ra[4], rb[4];
            #pragma unroll
            for (int a = 0; a < 4; a++) ra[a] = As[k * 65 + ty * 4 + a];
            #pragma unroll
            for (int b = 0; b < 4; b++) rb[b] = Bs[k * 64 + tx * 4 + b];
            #pragma unroll
            for (int a = 0; a < 4; a++)
                #pragma unroll
                for (int b = 0; b < 4; b++)
                    acc[a][b] += ra[a] * rb[b];
        }
        __syncthreads();
    }

    float* dstBase = (s == 0) ? g_q : (s == 1) ? g_k : g_v;
    #pragma unroll
    for (int a = 0; a < 4; a++) {
        int m  = m0 + ty * 4 + a;
        int bb = m >> 12;            // / 4096
        int n  = m & 4095;
        float* dst = dstBase + (((size_t)bb * NHn + h) * Nn + n) * HDn + tx * 4;
        #pragma unroll
        for (int b = 0; b < 4; b++)
            dst[b] = acc[a][b];
    }
}

// ---------------------------------------------------------------------------
// Kernel 3: Flash attention. Grid (N/64, B*NH). 256 threads, thread 4x4.
// K tile stored d-major with stride 65 (conflict-free transpose + reads);
// its buffer is reused for P between the two inner GEMMs.
// ---------------------------------------------------------------------------
__global__ void attn_kernel() {
    extern __shared__ float sh[];
    float* Qs  = sh;                  // 64*64       [i][d]
    float* Kst = sh + 4096;           // 64*65       [d][n] ; reused as Ps [i][j]
    float* Vs  = sh + 4096 + 4160;    // 64*64       [j][dd]

    int bh = blockIdx.y;
    int q0 = blockIdx.x * 64;
    const float* Q = g_q + (size_t)bh * Nn * HDn;
    const float* K = g_k + (size_t)bh * Nn * HDn;
    const float* V = g_v + (size_t)bh * Nn * HDn;

    int tid = threadIdx.x;
    int tx = tid & 15, ty = tid >> 4;

    #pragma unroll
    for (int l = 0; l < 16; l++) {
        int idx = tid + l * 256;
        Qs[idx] = Q[(size_t)q0 * 64 + idx];
    }

    float m[4], lsum[4], oacc[4][4];
    #pragma unroll
    for (int a = 0; a < 4; a++) {
        m[a] = -1e30f; lsum[a] = 0.f;
        #pragma unroll
        for (int b = 0; b < 4; b++) oacc[a][b] = 0.f;
    }
    const float scale = 0.125f;   // 1/sqrt(64)

    for (int kt = 0; kt < Nn; kt += 64) {
        __syncthreads();   // previous PV done before overwriting Kst/Vs
        #pragma unroll
        for (int l = 0; l < 16; l++) {
            int idx = tid + l * 256;
            int n = idx >> 6, d = idx & 63;
            Kst[d * 65 + n] = K[(size_t)(kt + n) * 64 + d];
            Vs[idx]         = V[(size_t)kt * 64 + idx];
        }
        __syncthreads();

        float s[4][4] = {};
        #pragma unroll 8
        for (int d = 0; d < 64; d++) {
            float qv[4], kv[4];
            #pragma unroll
            for (int a = 0; a < 4; a++) qv[a] = Qs[(ty * 4 + a) * 64 + d];
            #pragma unroll
            for (int b = 0; b < 4; b++) kv[b] = Kst[d * 65 + tx * 4 + b];
            #pragma unroll
            for (int a = 0; a < 4; a++)
                #pragma unroll
                for (int b = 0; b < 4; b++)
                    s[a][b] += qv[a] * kv[b];
        }

        // online softmax (row groups are lanes 0-15 / 16-31 of a warp)
        float p[4][4];
        #pragma unroll
        for (int a = 0; a < 4; a++) {
            #pragma unroll
            for (int b = 0; b < 4; b++) s[a][b] *= scale;
            float rm = fmaxf(fmaxf(s[a][0], s[a][1]), fmaxf(s[a][2], s[a][3]));
            #pragma unroll
            for (int off = 8; off; off >>= 1)
                rm = fmaxf(rm, __shfl_xor_sync(0xffffffffu, rm, off));
            float mnew = fmaxf(m[a], rm);
            float corr = __expf(m[a] - mnew);
            float rs = 0.f;
            #pragma unroll
            for (int b = 0; b < 4; b++) { p[a][b] = __expf(s[a][b] - mnew); rs += p[a][b]; }
            #pragma unroll
            for (int off = 8; off; off >>= 1)
                rs += __shfl_xor_sync(0xffffffffu, rs, off);
            lsum[a] = lsum[a] * corr + rs;
            m[a] = mnew;
            #pragma unroll
            for (int b = 0; b < 4; b++) oacc[a][b] *= corr;
        }

        __syncthreads();   // all threads done reading Kst
        float* Ps = Kst;
        #pragma unroll
        for (int a = 0; a < 4; a++)
            #pragma unroll
            for (int b = 0; b < 4; b++)
                Ps[(ty * 4 + a) * 65 + tx * 4 + b] = p[a][b];
        __syncthreads();

        #pragma unroll 8
        for (int j = 0; j < 64; j++) {
            float pv[4], vv[4];
            #pragma unroll
            for (int a = 0; a < 4; a++) pv[a] = Ps[(ty * 4 + a) * 65 + j];
            #pragma unroll
            for (int b = 0; b < 4; b++) vv[b] = Vs[j * 64 + tx * 4 + b];
            #pragma unroll
            for (int a = 0; a < 4; a++)
                #pragma unroll
                for (int b = 0; b < 4; b++)
                    oacc[a][b] += pv[a] * vv[b];
        }
    }

    // write O back as [b][n][h*64+dd]
    int bb = bh >> 2, h = bh & 3;
    float* Od = g_o + ((size_t)bb * Nn + q0) * Cn + h * 64;
    #pragma unroll
    for (int a = 0; a < 4; a++) {
        float inv = 1.f / lsum[a];
        int i = ty * 4 + a;
        #pragma unroll
        for (int b = 0; b < 4; b++)
            Od[(size_t)i * Cn + tx * 4 + b] = oacc[a][b] * inv;
    }
}

// ---------------------------------------------------------------------------
// Kernel 4: output projection + bias, writing transposed [B,C,N] directly.
// out[b,c,n] = sum_k o[b,n,k] * w_proj[c,k] + b_proj[c]
// Block tile: 64 channels x 64 tokens, thread 4x4 (rows=channels, cols=tokens)
// so the output stores are float4-coalesced along n.
// ---------------------------------------------------------------------------
__global__ void proj_kernel(const float* __restrict__ w,
                            const float* __restrict__ bias,
                            float* __restrict__ out) {
    __shared__ float Ws[16 * 65];   // [k][c]
    __shared__ float Os[16 * 65];   // [k][n]

    int n0 = blockIdx.x * 64;
    int c0 = blockIdx.y * 64;
    int bb = blockIdx.z;

    int tid = threadIdx.x;
    int tx = tid & 15, ty = tid >> 4;
    float acc[4][4] = {};

    const float* A = g_o + (size_t)bb * Nn * Cn;   // [n][k]
    for (int k0 = 0; k0 < 256; k0 += 16) {
        #pragma unroll
        for (int l = 0; l < 4; l++) {
            int idx = tid + l * 256;
            int r = idx >> 4, k = idx & 15;
            Ws[k * 65 + r] = w[(size_t)(c0 + r) * 256 + k0 + k];
            Os[k * 65 + r] = A[(size_t)(n0 + r) * 256 + k0 + k];
        }
        __syncthreads();
        #pragma unroll
        for (int k = 0; k < 16; k++) {
            float rc[4], rn[4];
            #pragma unroll
            for (int a = 0; a < 4; a++) rc[a] = Ws[k * 65 + ty * 4 + a];
            #pragma unroll
            for (int b = 0; b < 4; b++) rn[b] = Os[k * 65 + tx * 4 + b];
            #pragma unroll
            for (int a = 0; a < 4; a++)
                #pragma unroll
                for (int b = 0; b < 4; b++)
                    acc[a][b] += rc[a] * rn[b];
        }
        __syncthreads();
    }

    #pragma unroll
    for (int a = 0; a < 4; a++) {
        int c = c0 + ty * 4 + a;
        float bv = bias[c];
        float4 v = make_float4(acc[a][0] + bv, acc[a][1] + bv,
                               acc[a][2] + bv, acc[a][3] + bv);
        *(float4*)&out[((size_t)bb * Cn + c) * Nn + n0 + tx * 4] = v;
    }
}

// ---------------------------------------------------------------------------
extern "C" void kernel_launch(void* const* d_in, const int* in_sizes, int n_in,
                              void* d_out, int out_size) {
    const float* x      = (const float*)d_in[0];
    const float* ln_g   = (const float*)d_in[1];
    const float* ln_b   = (const float*)d_in[2];
    const float* w_qkv  = (const float*)d_in[3];
    const float* w_proj = (const float*)d_in[4];
    const float* b_proj = (const float*)d_in[5];
    float* out = (float*)d_out;

    ln_kernel<<<Bn * (Nn / 32), dim3(32, 8)>>>(x, ln_g, ln_b);
    qkv_kernel<<<dim3(12, (Bn * Nn) / 64), 256>>>(w_qkv);

    const int attn_smem = (4096 + 64 * 65 + 4096) * sizeof(float);  // 49408 B
    cudaFuncSetAttribute(attn_kernel, cudaFuncAttributeMaxDynamicSharedMemorySize, attn_smem);
    attn_kernel<<<dim3(Nn / 64, Bn * NHn), 256, attn_smem>>>();

    proj_kernel<<<dim3(Nn / 64, Cn / 64, Bn), 256>>>(w_proj, b_proj, out);
}

// round 2
// speedup vs baseline: 1.1003x; 1.1003x over previous
#include <cuda_runtime.h>

#define Bn   4
#define Cn   256
#define Nn   4096
#define NHn  4
#define HDn  64

typedef unsigned long long u64;

// Scratch (device globals; no runtime allocation allowed)
__device__ float g_tln[Bn * Nn * Cn];            // LN'd tokens [b][n][c]
__device__ float g_q[Bn * NHn * Nn * HDn];       // [bh][n][d]
__device__ float g_k[Bn * NHn * Nn * HDn];
__device__ float g_v[Bn * NHn * Nn * HDn];
__device__ float g_o[Bn * Nn * Cn];              // attention out [b][n][c]

// ---- packed f32x2 helpers (FFMA2 path: 2x fp32 FMA throughput, exact fp32) ----
__device__ __forceinline__ u64 f2fma(u64 a, u64 b, u64 c) {
    u64 d;
    asm("fma.rn.f32x2 %0, %1, %2, %3;" : "=l"(d) : "l"(a), "l"(b), "l"(c));
    return d;
}
__device__ __forceinline__ u64 f2mul(u64 a, u64 b) {
    u64 d;
    asm("mul.rn.f32x2 %0, %1, %2;" : "=l"(d) : "l"(a), "l"(b));
    return d;
}
__device__ __forceinline__ u64 f2pack(float lo, float hi) {
    u64 d;
    asm("mov.b64 %0, {%1, %2};" : "=l"(d) : "f"(lo), "f"(hi));
    return d;
}
__device__ __forceinline__ float2 f2unpack(u64 v) {
    float lo, hi;
    asm("mov.b64 {%0, %1}, %2;" : "=f"(lo), "=f"(hi) : "l"(v));
    return make_float2(lo, hi);
}

// ---------------------------------------------------------------------------
// Kernel 1: LayerNorm over C with NCHW -> [B,N,C] transpose.
// ---------------------------------------------------------------------------
__global__ void ln_kernel(const float* __restrict__ x,
                          const float* __restrict__ gamma,
                          const float* __restrict__ beta) {
    __shared__ float sm[256 * 33];
    __shared__ float red[2][8][32];
    __shared__ float sMean[32], sRstd[32];

    int blk = blockIdx.x;
    int bb  = blk >> 7;
    int n0  = (blk & 127) * 32;
    int tx  = threadIdx.x;
    int ty  = threadIdx.y;

    const float* xb = x + (size_t)bb * Cn * Nn;
    for (int c = ty; c < 256; c += 8)
        sm[c * 33 + tx] = xb[(size_t)c * Nn + n0 + tx];
    __syncthreads();

    float s = 0.f, s2 = 0.f;
    for (int c = ty; c < 256; c += 8) {
        float v = sm[c * 33 + tx];
        s += v; s2 += v * v;
    }
    red[0][ty][tx] = s;
    red[1][ty][tx] = s2;
    __syncthreads();

    if (ty == 0) {
        float a = 0.f, b2 = 0.f;
        #pragma unroll
        for (int i = 0; i < 8; i++) { a += red[0][i][tx]; b2 += red[1][i][tx]; }
        float mean = a * (1.f / 256.f);
        float var  = b2 * (1.f / 256.f) - mean * mean;
        sMean[tx] = mean;
        sRstd[tx] = rsqrtf(var + 1e-5f);
    }
    __syncthreads();

    int c = ty * 32 + tx;
    float gc = gamma[c], bc = beta[c];
    float* out = g_tln + ((size_t)bb * Nn + n0) * Cn;
    #pragma unroll 8
    for (int t = 0; t < 32; t++) {
        float v = (sm[c * 33 + t] - sMean[t]) * sRstd[t] * gc + bc;
        out[(size_t)t * Cn + c] = v;
    }
}

// ---------------------------------------------------------------------------
// Kernel 2: QKV GEMM  [16384,256] @ [256,768] -> g_q/g_k/g_v [bh][n][d]
// ---------------------------------------------------------------------------
__global__ void qkv_kernel(const float* __restrict__ w) {
    __shared__ float As[16 * 65];    // [k][m]
    __shared__ float Bs[16 * 64];    // [k][n]

    int s  = blockIdx.x >> 2;
    int h  = blockIdx.x & 3;
    int n0 = blockIdx.x * 64;
    int m0 = blockIdx.y * 64;

    int tid = threadIdx.x;
    int tx = tid & 15, ty = tid >> 4;
    float acc[4][4] = {};

    const float* A = g_tln + (size_t)m0 * Cn;
    for (int k0 = 0; k0 < 256; k0 += 16) {
        #pragma unroll
        for (int l = 0; l < 4; l++) {
            int idx = tid + l * 256;
            int m = idx >> 4, k = idx & 15;
            As[k * 65 + m] = A[(size_t)m * Cn + k0 + k];
        }
        #pragma unroll
        for (int l = 0; l < 4; l++) {
            int idx = tid + l * 256;
            int k = idx >> 6, n = idx & 63;
            Bs[k * 64 + n] = w[(size_t)(k0 + k) * 768 + n0 + n];
        }
        __syncthreads();
        #pragma unroll
        for (int k = 0; k < 16; k++) {
            float ra[4], rb[4];
            #pragma unroll
            for (int a = 0; a < 4; a++) ra[a] = As[k * 65 + ty * 4 + a];
            #pragma unroll
            for (int b = 0; b < 4; b++) rb[b] = Bs[k * 64 + tx * 4 + b];
            #pragma unroll
            for (int a = 0; a < 4; a++)
                #pragma unroll
                for (int b = 0; b < 4; b++)
                    acc[a][b] += ra[a] * rb[b];
        }
        __syncthreads();
    }

    float* dstBase = (s == 0) ? g_q : (s == 1) ? g_k : g_v;
    #pragma unroll
    for (int a = 0; a < 4; a++) {
        int m  = m0 + ty * 4 + a;
        int bb = m >> 12;
        int n  = m & 4095;
        float* dst = dstBase + (((size_t)bb * NHn + h) * Nn + n) * HDn + tx * 4;
        #pragma unroll
        for (int b = 0; b < 4; b++)
            dst[b] = acc[a][b];
    }
}

// ---------------------------------------------------------------------------
// Kernel 3: Flash attention with packed f32x2 FMAs.
// Grid (N/64, B*NH). 256 threads.
//   Q rows  i = ty*4 + a   (a=0..3)
//   K cols  j = tx + 16*b  (b=0..3)  -> lane-adjacent addrs step 4 banks
//   QK^T packs along d (ulonglong2 loads, no pack instr)
//   P stored transposed [j][i] (stride 68) so PV packs along i
// ---------------------------------------------------------------------------
#define KS 68   // K/P row stride (floats): 272B steps -> conflict-free LDS.128

__global__ __launch_bounds__(256) void attn_kernel() {
    extern __shared__ float sh[];
    float* Qs = sh;                    // 64*64  [i][d]
    float* Ks = sh + 4096;             // 64*KS  [j][d] ; reused as Ps [j][i]
    float* Vs = sh + 4096 + 64 * KS;   // 64*64  [j][dd]

    int bh = blockIdx.y;
    int q0 = blockIdx.x * 64;
    const float* Q = g_q + (size_t)bh * Nn * HDn;
    const float* K = g_k + (size_t)bh * Nn * HDn;
    const float* V = g_v + (size_t)bh * Nn * HDn;

    int tid = threadIdx.x;
    int tx = tid & 15, ty = tid >> 4;

    // load Q tile (row-major, stride 64)
    #pragma unroll
    for (int p = 0; p < 4; p++) {
        int idx4 = (p * 256 + tid) * 4;
        *(float4*)&Qs[idx4] = *(const float4*)&Q[(size_t)q0 * 64 + idx4];
    }

    float m[4], lsum[4];
    u64 o2[2][4];                      // packed along i: (i0,i1),(i2,i3) x 4 dd
    #pragma unroll
    for (int a = 0; a < 4; a++) { m[a] = -1e30f; lsum[a] = 0.f; }
    #pragma unroll
    for (int ap = 0; ap < 2; ap++)
        #pragma unroll
        for (int b = 0; b < 4; b++) o2[ap][b] = 0ull;

    const float scale = 0.125f;        // 1/sqrt(64)

    for (int kt = 0; kt < Nn; kt += 64) {
        __syncthreads();               // prev PV done with Ps/Vs
        // load K tile -> Ks[j][d] (stride KS), V tile -> Vs[j][dd] (stride 64)
        #pragma unroll
        for (int p = 0; p < 4; p++) {
            int idx4 = (p * 256 + tid) * 4;
            int n = idx4 >> 6, d = idx4 & 63;
            *(float4*)&Ks[n * KS + d] = *(const float4*)&K[(size_t)(kt + n) * 64 + d];
            *(float4*)&Vs[idx4]       = *(const float4*)&V[(size_t)kt * 64 + idx4];
        }
        __syncthreads();

        // ---- QK^T : acc packed along d ----
        u64 acc2[4][4];
        #pragma unroll
        for (int a = 0; a < 4; a++)
            #pragma unroll
            for (int b = 0; b < 4; b++) acc2[a][b] = 0ull;

        #pragma unroll 4
        for (int d = 0; d < 64; d += 4) {
            ulonglong2 qp[4], kp[4];
            #pragma unroll
            for (int a = 0; a < 4; a++)
                qp[a] = *(const ulonglong2*)&Qs[(ty * 4 + a) * 64 + d];
            #pragma unroll
            for (int b = 0; b < 4; b++)
                kp[b] = *(const ulonglong2*)&Ks[(tx + 16 * b) * KS + d];
            #pragma unroll
            for (int a = 0; a < 4; a++)
                #pragma unroll
                for (int b = 0; b < 4; b++) {
                    acc2[a][b] = f2fma(qp[a].x, kp[b].x, acc2[a][b]);
                    acc2[a][b] = f2fma(qp[a].y, kp[b].y, acc2[a][b]);
                }
        }

        // ---- online softmax (scalar; rows span 16 tx lanes x 4 b) ----
        float p[4][4], corr[4];
        #pragma unroll
        for (int a = 0; a < 4; a++) {
            float s[4];
            #pragma unroll
            for (int b = 0; b < 4; b++) {
                float2 uv = f2unpack(acc2[a][b]);
                s[b] = (uv.x + uv.y) * scale;
            }
            float rm = fmaxf(fmaxf(s[0], s[1]), fmaxf(s[2], s[3]));
            #pragma unroll
            for (int off = 8; off; off >>= 1)
                rm = fmaxf(rm, __shfl_xor_sync(0xffffffffu, rm, off));
            float mnew = fmaxf(m[a], rm);
            corr[a] = __expf(m[a] - mnew);
            float rs = 0.f;
            #pragma unroll
            for (int b = 0; b < 4; b++) { p[a][b] = __expf(s[b] - mnew); rs += p[a][b]; }
            #pragma unroll
            for (int off = 8; off; off >>= 1)
                rs += __shfl_xor_sync(0xffffffffu, rs, off);
            lsum[a] = lsum[a] * corr[a] + rs;
            m[a] = mnew;
        }
        {
            u64 c01 = f2pack(corr[0], corr[1]);
            u64 c23 = f2pack(corr[2], corr[3]);
            #pragma unroll
            for (int b = 0; b < 4; b++) {
                o2[0][b] = f2mul(o2[0][b], c01);
                o2[1][b] = f2mul(o2[1][b], c23);
            }
        }

        __syncthreads();               // all lanes done reading Ks
        // store P transposed: Ps[j][i], j = tx+16b, i = ty*4..ty*4+3
        float* Ps = Ks;
        #pragma unroll
        for (int b = 0; b < 4; b++) {
            float4 v = make_float4(p[0][b], p[1][b], p[2][b], p[3][b]);
            *(float4*)&Ps[(tx + 16 * b) * KS + ty * 4] = v;
        }
        __syncthreads();

        // ---- PV : o packed along i ----
        #pragma unroll 4
        for (int j = 0; j < 64; j++) {
            ulonglong2 pp = *(const ulonglong2*)&Ps[j * KS + ty * 4];
            float4 vv = *(const float4*)&Vs[j * 64 + tx * 4];
            u64 v0 = f2pack(vv.x, vv.x);
            u64 v1 = f2pack(vv.y, vv.y);
            u64 v2 = f2pack(vv.z, vv.z);
            u64 v3 = f2pack(vv.w, vv.w);
            o2[0][0] = f2fma(pp.x, v0, o2[0][0]);
            o2[0][1] = f2fma(pp.x, v1, o2[0][1]);
            o2[0][2] = f2fma(pp.x, v2, o2[0][2]);
            o2[0][3] = f2fma(pp.x, v3, o2[0][3]);
            o2[1][0] = f2fma(pp.y, v0, o2[1][0]);
            o2[1][1] = f2fma(pp.y, v1, o2[1][1]);
            o2[1][2] = f2fma(pp.y, v2, o2[1][2]);
            o2[1][3] = f2fma(pp.y, v3, o2[1][3]);
        }
    }

    // write O back as [b][n][h*64+dd], dd = tx*4+b
    int bb = bh >> 2, h = bh & 3;
    float* Od = g_o + ((size_t)bb * Nn + q0) * Cn + h * 64;
    float inv[4];
    #pragma unroll
    for (int a = 0; a < 4; a++) inv[a] = 1.f / lsum[a];
    #pragma unroll
    for (int ap = 0; ap < 2; ap++) {
        float4 r0, r1;   // rows 2ap and 2ap+1
        float2 u;
        u = f2unpack(o2[ap][0]); r0.x = u.x * inv[2*ap]; r1.x = u.y * inv[2*ap+1];
        u = f2unpack(o2[ap][1]); r0.y = u.x * inv[2*ap]; r1.y = u.y * inv[2*ap+1];
        u = f2unpack(o2[ap][2]); r0.z = u.x * inv[2*ap]; r1.z = u.y * inv[2*ap+1];
        u = f2unpack(o2[ap][3]); r0.w = u.x * inv[2*ap]; r1.w = u.y * inv[2*ap+1];
        int i0 = ty * 4 + 2 * ap;
        *(float4*)&Od[(size_t)i0 * Cn + tx * 4]       = r0;
        *(float4*)&Od[(size_t)(i0 + 1) * Cn + tx * 4] = r1;
    }
}

// ---------------------------------------------------------------------------
// Kernel 4: output projection + bias -> transposed [B,C,N] output.
// ---------------------------------------------------------------------------
__global__ void proj_kernel(const float* __restrict__ w,
                            const float* __restrict__ bias,
                            float* __restrict__ out) {
    __shared__ float Ws[16 * 65];   // [k][c]
    __shared__ float Os[16 * 65];   // [k][n]

    int n0 = blockIdx.x * 64;
    int c0 = blockIdx.y * 64;
    int bb = blockIdx.z;

    int tid = threadIdx.x;
    int tx = tid & 15, ty = tid >> 4;
    float acc[4][4] = {};

    const float* A = g_o + (size_t)bb * Nn * Cn;
    for (int k0 = 0; k0 < 256; k0 += 16) {
        #pragma unroll
        for (int l = 0; l < 4; l++) {
            int idx = tid + l * 256;
            int r = idx >> 4, k = idx & 15;
            Ws[k * 65 + r] = w[(size_t)(c0 + r) * 256 + k0 + k];
            Os[k * 65 + r] = A[(size_t)(n0 + r) * 256 + k0 + k];
        }
        __syncthreads();
        #pragma unroll
        for (int k = 0; k < 16; k++) {
            float rc[4], rn[4];
            #pragma unroll
            for (int a = 0; a < 4; a++) rc[a] = Ws[k * 65 + ty * 4 + a];
            #pragma unroll
            for (int b = 0; b < 4; b++) rn[b] = Os[k * 65 + tx * 4 + b];
            #pragma unroll
            for (int a = 0; a < 4; a++)
                #pragma unroll
                for (int b = 0; b < 4; b++)
                    acc[a][b] += rc[a] * rn[b];
        }
        __syncthreads();
    }

    #pragma unroll
    for (int a = 0; a < 4; a++) {
        int c = c0 + ty * 4 + a;
        float bv = bias[c];
        float4 v = make_float4(acc[a][0] + bv, acc[a][1] + bv,
                               acc[a][2] + bv, acc[a][3] + bv);
        *(float4*)&out[((size_t)bb * Cn + c) * Nn + n0 + tx * 4] = v;
    }
}

// ---------------------------------------------------------------------------
extern "C" void kernel_launch(void* const* d_in, const int* in_sizes, int n_in,
                              void* d_out, int out_size) {
    const float* x      = (const float*)d_in[0];
    const float* ln_g   = (const float*)d_in[1];
    const float* ln_b   = (const float*)d_in[2];
    const float* w_qkv  = (const float*)d_in[3];
    const float* w_proj = (const float*)d_in[4];
    const float* b_proj = (const float*)d_in[5];
    float* out = (float*)d_out;

    ln_kernel<<<Bn * (Nn / 32), dim3(32, 8)>>>(x, ln_g, ln_b);
    qkv_kernel<<<dim3(12, (Bn * Nn) / 64), 256>>>(w_qkv);

    const int attn_smem = (4096 + 64 * KS + 4096) * sizeof(float);  // 50176 B
    cudaFuncSetAttribute(attn_kernel, cudaFuncAttributeMaxDynamicSharedMemorySize, attn_smem);
    attn_kernel<<<dim3(Nn / 64, Bn * NHn), 256, attn_smem>>>();

    proj_kernel<<<dim3(Nn / 64, Cn / 64, Bn), 256>>>(w_proj, b_proj, out);
}

// round 3
// speedup vs baseline: 1.2427x; 1.1294x over previous
#include <cuda_runtime.h>

#define Bn   4
#define Cn   256
#define Nn   4096
#define NHn  4
#define HDn  64

typedef unsigned long long u64;
typedef unsigned int u32;

// Scratch (device globals; no runtime allocation allowed)
__device__ float g_tln[Bn * Nn * Cn];            // LN'd tokens [b][n][c]
__device__ float g_q[Bn * NHn * Nn * HDn];       // [bh][n][d]
__device__ float g_k[Bn * NHn * HDn * Nn];       // [bh][d][n]  (d-major!)
__device__ float g_v[Bn * NHn * Nn * HDn];       // [bh][n][d]
__device__ float g_o[Bn * Nn * Cn];              // attention out [b][n][c]

// ---- packed f32x2 helpers ----
__device__ __forceinline__ u64 f2fma(u64 a, u64 b, u64 c) {
    u64 d;
    asm("fma.rn.f32x2 %0, %1, %2, %3;" : "=l"(d) : "l"(a), "l"(b), "l"(c));
    return d;
}
__device__ __forceinline__ u64 f2mul(u64 a, u64 b) {
    u64 d;
    asm("mul.rn.f32x2 %0, %1, %2;" : "=l"(d) : "l"(a), "l"(b));
    return d;
}
__device__ __forceinline__ u64 f2pack(float lo, float hi) {
    u64 d;
    asm("mov.b64 %0, {%1, %2};" : "=l"(d) : "f"(lo), "f"(hi));
    return d;
}
__device__ __forceinline__ u64 f2dup(float x) {
    u64 d;
    asm("mov.b64 %0, {%1, %1};" : "=l"(d) : "f"(x));
    return d;
}
__device__ __forceinline__ float2 f2unpack(u64 v) {
    float lo, hi;
    asm("mov.b64 {%0, %1}, %2;" : "=f"(lo), "=f"(hi) : "l"(v));
    return make_float2(lo, hi);
}

__device__ __forceinline__ u32 sptr(const void* p) {
    return (u32)__cvta_generic_to_shared(p);
}
#define CPA16(dst, src) \
    asm volatile("cp.async.cg.shared.global [%0], [%1], 16;" :: "r"(dst), "l"(src))
#define CP_COMMIT asm volatile("cp.async.commit_group;" ::: "memory")
#define CP_WAIT0  asm volatile("cp.async.wait_group 0;" ::: "memory")

// ---------------------------------------------------------------------------
// Kernel 1: LayerNorm over C with NCHW -> [B,N,C] transpose.
// ---------------------------------------------------------------------------
__global__ void ln_kernel(const float* __restrict__ x,
                          const float* __restrict__ gamma,
                          const float* __restrict__ beta) {
    __shared__ float sm[256 * 33];
    __shared__ float red[2][8][32];
    __shared__ float sMean[32], sRstd[32];

    int blk = blockIdx.x;
    int bb  = blk >> 7;
    int n0  = (blk & 127) * 32;
    int tx  = threadIdx.x;
    int ty  = threadIdx.y;

    const float* xb = x + (size_t)bb * Cn * Nn;
    for (int c = ty; c < 256; c += 8)
        sm[c * 33 + tx] = xb[(size_t)c * Nn + n0 + tx];
    __syncthreads();

    float s = 0.f, s2 = 0.f;
    for (int c = ty; c < 256; c += 8) {
        float v = sm[c * 33 + tx];
        s += v; s2 += v * v;
    }
    red[0][ty][tx] = s;
    red[1][ty][tx] = s2;
    __syncthreads();

    if (ty == 0) {
        float a = 0.f, b2 = 0.f;
        #pragma unroll
        for (int i = 0; i < 8; i++) { a += red[0][i][tx]; b2 += red[1][i][tx]; }
        float mean = a * (1.f / 256.f);
        float var  = b2 * (1.f / 256.f) - mean * mean;
        sMean[tx] = mean;
        sRstd[tx] = rsqrtf(var + 1e-5f);
    }
    __syncthreads();

    int c = ty * 32 + tx;
    float gc = gamma[c], bc = beta[c];
    float* out = g_tln + ((size_t)bb * Nn + n0) * Cn;
    #pragma unroll 8
    for (int t = 0; t < 32; t++) {
        float v = (sm[c * 33 + t] - sMean[t]) * sRstd[t] * gc + bc;
        out[(size_t)t * Cn + c] = v;
    }
}

// ---------------------------------------------------------------------------
// Kernel 2: QKV GEMM. q,v written [bh][n][d]; k written d-major [bh][d][n].
// ---------------------------------------------------------------------------
__global__ void qkv_kernel(const float* __restrict__ w) {
    __shared__ float As[16 * 65];    // [k][m]
    __shared__ float Bs[16 * 64];    // [k][n]

    int s  = blockIdx.x >> 2;
    int h  = blockIdx.x & 3;
    int n0 = blockIdx.x * 64;
    int m0 = blockIdx.y * 64;

    int tid = threadIdx.x;
    int tx = tid & 15, ty = tid >> 4;
    float acc[4][4] = {};

    const float* A = g_tln + (size_t)m0 * Cn;
    for (int k0 = 0; k0 < 256; k0 += 16) {
        #pragma unroll
        for (int l = 0; l < 4; l++) {
            int idx = tid + l * 256;
            int m = idx >> 4, k = idx & 15;
            As[k * 65 + m] = A[(size_t)m * Cn + k0 + k];
        }
        #pragma unroll
        for (int l = 0; l < 4; l++) {
            int idx = tid + l * 256;
            int k = idx >> 6, n = idx & 63;
            Bs[k * 64 + n] = w[(size_t)(k0 + k) * 768 + n0 + n];
        }
        __syncthreads();
        #pragma unroll
        for (int k = 0; k < 16; k++) {
            float ra[4], rb[4];
            #pragma unroll
            for (int a = 0; a < 4; a++) ra[a] = As[k * 65 + ty * 4 + a];
            #pragma unroll
            for (int b = 0; b < 4; b++) rb[b] = Bs[k * 64 + tx * 4 + b];
            #pragma unroll
            for (int a = 0; a < 4; a++)
                #pragma unroll
                for (int b = 0; b < 4; b++)
                    acc[a][b] += ra[a] * rb[b];
        }
        __syncthreads();
    }

    #pragma unroll
    for (int a = 0; a < 4; a++) {
        int m  = m0 + ty * 4 + a;
        int bb = m >> 12;
        int n  = m & 4095;
        if (s == 1) {
            // K: d-major [bh][d][n]
            #pragma unroll
            for (int b = 0; b < 4; b++) {
                int d = tx * 4 + b;
                g_k[(((size_t)bb * NHn + h) * HDn + d) * Nn + n] = acc[a][b];
            }
        } else {
            float* dstBase = (s == 0) ? g_q : g_v;
            float* dst = dstBase + (((size_t)bb * NHn + h) * Nn + n) * HDn + tx * 4;
            #pragma unroll
            for (int b = 0; b < 4; b++)
                dst[b] = acc[a][b];
        }
    }
}

// ---------------------------------------------------------------------------
// Kernel 3: Flash attention, 256q x 64k tile, 8x8 thread tiles, f32x2,
// cp.async double-buffered K/V.
//   tx = tid&7, ty = tid>>3
//   QK: i pairs = ty*8 + 2a (a 0..3);  j = tx*4 + jj%4 + (jj/4)*32
//   PV: rows i = ty*8 + r;  dd pairs = tx*4 (+32)
// ---------------------------------------------------------------------------
#define QS  258   // Qt row stride (floats)
#define KTS 68    // Kt row stride
#define PS  260   // Ps row stride

__global__ __launch_bounds__(256, 1) void attn_kernel() {
    extern __shared__ float sh[];
    float* Qt  = sh;                         // [64][QS]   Qt[d][i], pre-scaled
    float* Kt0 = Qt + 64 * QS;               // 2 x [64][KTS]  Kt[d][j]
    float* Vs0 = Kt0 + 2 * 64 * KTS;         // 2 x [64][64]   Vs[j][dd]
    float* Ps  = Vs0 + 2 * 64 * 64;          // [64][PS]   Ps[j][i]

    const int bh  = blockIdx.y;
    const int q0  = blockIdx.x * 256;
    const int tid = threadIdx.x;
    const int tx  = tid & 7;
    const int ty  = tid >> 3;

    const float* Qg = g_q + (size_t)bh * Nn * HDn;
    const float* Kg = g_k + (size_t)bh * HDn * Nn;   // [d][n]
    const float* Vg = g_v + (size_t)bh * Nn * HDn;

    // load Qt transposed, fold in softmax scale (exact: 2^-3)
    {
        const float* qrow = Qg + (size_t)(q0 + tid) * HDn;
        #pragma unroll
        for (int c = 0; c < 16; c++) {
            float4 v = *(const float4*)(qrow + c * 4);
            Qt[(c * 4 + 0) * QS + tid] = v.x * 0.125f;
            Qt[(c * 4 + 1) * QS + tid] = v.y * 0.125f;
            Qt[(c * 4 + 2) * QS + tid] = v.z * 0.125f;
            Qt[(c * 4 + 3) * QS + tid] = v.w * 0.125f;
        }
    }

    // cp.async prefetch of one 64-key K/V tile into buffer `buf`
    const int pf_d  = tid >> 2;          // row (d for K, j for V)
    const int pf_co = (tid & 3) * 64;    // byte offset within 256B row

    float m[8], l[8];
    u64 o2[8][4];
    #pragma unroll
    for (int r = 0; r < 8; r++) {
        m[r] = -1e30f; l[r] = 0.f;
        #pragma unroll
        for (int c = 0; c < 4; c++) o2[r][c] = 0ull;
    }

    // prefetch tile 0
    {
        const char* ks = (const char*)(Kg + (size_t)pf_d * Nn) + pf_co;
        u32 kd = sptr(Kt0 + pf_d * KTS) + pf_co;
        const char* vs = (const char*)(Vg + (size_t)pf_d * HDn) + pf_co;
        u32 vd = sptr(Vs0 + pf_d * 64) + pf_co;
        #pragma unroll
        for (int k = 0; k < 4; k++) {
            CPA16(kd + k * 16, ks + k * 16);
            CPA16(vd + k * 16, vs + k * 16);
        }
        CP_COMMIT;
    }

    for (int t = 0; t < 64; t++) {
        int cur = t & 1;
        CP_WAIT0;
        __syncthreads();   // buf cur ready; everyone done with buf cur^1 & Ps

        if (t + 1 < 64) {
            int ktn = (t + 1) * 64;
            const char* ks = (const char*)(Kg + (size_t)pf_d * Nn + ktn) + pf_co;
            u32 kd = sptr(Kt0 + (cur ^ 1) * 64 * KTS + pf_d * KTS) + pf_co;
            const char* vs = (const char*)(Vg + (size_t)(ktn + pf_d) * HDn) + pf_co;
            u32 vd = sptr(Vs0 + (cur ^ 1) * 64 * 64 + pf_d * 64) + pf_co;
            #pragma unroll
            for (int k = 0; k < 4; k++) {
                CPA16(kd + k * 16, ks + k * 16);
                CPA16(vd + k * 16, vs + k * 16);
            }
            CP_COMMIT;
        }

        const float* Kc = Kt0 + cur * 64 * KTS;
        const float* Vc = Vs0 + cur * 64 * 64;

        // ---- QK^T: acc2[a][jj] packed along i ----
        u64 acc[4][8];
        #pragma unroll
        for (int a = 0; a < 4; a++)
            #pragma unroll
            for (int jj = 0; jj < 8; jj++) acc[a][jj] = 0ull;

        #pragma unroll 8
        for (int d = 0; d < 64; d++) {
            u64 q2[4];
            #pragma unroll
            for (int a = 0; a < 4; a++)
                q2[a] = *(const u64*)&Qt[d * QS + ty * 8 + 2 * a];
            float4 k0 = *(const float4*)&Kc[d * KTS + tx * 4];
            float4 k1 = *(const float4*)&Kc[d * KTS + tx * 4 + 32];
            u64 kd[8];
            kd[0] = f2dup(k0.x); kd[1] = f2dup(k0.y);
            kd[2] = f2dup(k0.z); kd[3] = f2dup(k0.w);
            kd[4] = f2dup(k1.x); kd[5] = f2dup(k1.y);
            kd[6] = f2dup(k1.z); kd[7] = f2dup(k1.w);
            #pragma unroll
            for (int a = 0; a < 4; a++)
                #pragma unroll
                for (int jj = 0; jj < 8; jj++)
                    acc[a][jj] = f2fma(q2[a], kd[jj], acc[a][jj]);
        }

        // ---- online softmax (rows 2a, 2a+1 per a; reduce over 8 tx lanes) ----
        #pragma unroll
        for (int a = 0; a < 4; a++) {
            float s0[8], s1[8];
            #pragma unroll
            for (int jj = 0; jj < 8; jj++) {
                float2 u = f2unpack(acc[a][jj]);
                s0[jj] = u.x; s1[jj] = u.y;
            }
            float rm0 = s0[0], rm1 = s1[0];
            #pragma unroll
            for (int jj = 1; jj < 8; jj++) {
                rm0 = fmaxf(rm0, s0[jj]); rm1 = fmaxf(rm1, s1[jj]);
            }
            #pragma unroll
            for (int off = 4; off; off >>= 1) {
                rm0 = fmaxf(rm0, __shfl_xor_sync(0xffffffffu, rm0, off));
                rm1 = fmaxf(rm1, __shfl_xor_sync(0xffffffffu, rm1, off));
            }
            int r0 = 2 * a, r1 = 2 * a + 1;
            float mn0 = fmaxf(m[r0], rm0), mn1 = fmaxf(m[r1], rm1);
            float c0 = __expf(m[r0] - mn0), c1 = __expf(m[r1] - mn1);
            float p0[8], p1[8];
            float rs0 = 0.f, rs1 = 0.f;
            #pragma unroll
            for (int jj = 0; jj < 8; jj++) {
                p0[jj] = __expf(s0[jj] - mn0); rs0 += p0[jj];
                p1[jj] = __expf(s1[jj] - mn1); rs1 += p1[jj];
            }
            #pragma unroll
            for (int off = 4; off; off >>= 1) {
                rs0 += __shfl_xor_sync(0xffffffffu, rs0, off);
                rs1 += __shfl_xor_sync(0xffffffffu, rs1, off);
            }
            l[r0] = l[r0] * c0 + rs0; m[r0] = mn0;
            l[r1] = l[r1] * c1 + rs1; m[r1] = mn1;
            u64 cd0 = f2dup(c0), cd1 = f2dup(c1);
            #pragma unroll
            for (int c = 0; c < 4; c++) {
                o2[r0][c] = f2mul(o2[r0][c], cd0);
                o2[r1][c] = f2mul(o2[r1][c], cd1);
            }
            // store P transposed: Ps[j][i-pair]
            #pragma unroll
            for (int jj = 0; jj < 8; jj++) {
                int j = tx * 4 + (jj & 3) + (jj >> 2) * 32;
                *(u64*)&Ps[j * PS + ty * 8 + 2 * a] = f2pack(p0[jj], p1[jj]);
            }
        }
        __syncthreads();   // P visible to all

        // ---- PV: o2 packed along dd ----
        #pragma unroll 4
        for (int j = 0; j < 64; j++) {
            u64 pd[8];
            #pragma unroll
            for (int a = 0; a < 4; a++) {
                u64 pp = *(const u64*)&Ps[j * PS + ty * 8 + 2 * a];
                float2 u = f2unpack(pp);
                pd[2 * a]     = f2dup(u.x);
                pd[2 * a + 1] = f2dup(u.y);
            }
            ulonglong2 v0 = *(const ulonglong2*)&Vc[j * 64 + tx * 4];
            ulonglong2 v1 = *(const ulonglong2*)&Vc[j * 64 + tx * 4 + 32];
            #pragma unroll
            for (int r = 0; r < 8; r++) {
                o2[r][0] = f2fma(pd[r], v0.x, o2[r][0]);
                o2[r][1] = f2fma(pd[r], v0.y, o2[r][1]);
                o2[r][2] = f2fma(pd[r], v1.x, o2[r][2]);
                o2[r][3] = f2fma(pd[r], v1.y, o2[r][3]);
            }
        }
    }

    // finalize: write O as [b][n][h*64+dd]
    int bb = bh >> 2, h = bh & 3;
    #pragma unroll
    for (int r = 0; r < 8; r++) {
        float inv = 1.f / l[r];
        int i = q0 + ty * 8 + r;
        float* Od = g_o + ((size_t)bb * Nn + i) * Cn + h * 64;
        float2 u0 = f2unpack(o2[r][0]), u1 = f2unpack(o2[r][1]);
        float4 w0 = make_float4(u0.x * inv, u0.y * inv, u1.x * inv, u1.y * inv);
        *(float4*)&Od[tx * 4] = w0;
        u0 = f2unpack(o2[r][2]); u1 = f2unpack(o2[r][3]);
        float4 w1 = make_float4(u0.x * inv, u0.y * inv, u1.x * inv, u1.y * inv);
        *(float4*)&Od[tx * 4 + 32] = w1;
    }
}

// ---------------------------------------------------------------------------
// Kernel 4: output projection + bias -> transposed [B,C,N] output.
// ---------------------------------------------------------------------------
__global__ void proj_kernel(const float* __restrict__ w,
                            const float* __restrict__ bias,
                            float* __restrict__ out) {
    __shared__ float Ws[16 * 65];   // [k][c]
    __shared__ float Os[16 * 65];   // [k][n]

    int n0 = blockIdx.x * 64;
    int c0 = blockIdx.y * 64;
    int bb = blockIdx.z;

    int tid = threadIdx.x;
    int tx = tid & 15, ty = tid >> 4;
    float acc[4][4] = {};

    const float* A = g_o + (size_t)bb * Nn * Cn;
    for (int k0 = 0; k0 < 256; k0 += 16) {
        #pragma unroll
        for (int l = 0; l < 4; l++) {
            int idx = tid + l * 256;
            int r = idx >> 4, k = idx & 15;
            Ws[k * 65 + r] = w[(size_t)(c0 + r) * 256 + k0 + k];
            Os[k * 65 + r] = A[(size_t)(n0 + r) * 256 + k0 + k];
        }
        __syncthreads();
        #pragma unroll
        for (int k = 0; k < 16; k++) {
            float rc[4], rn[4];
            #pragma unroll
            for (int a = 0; a < 4; a++) rc[a] = Ws[k * 65 + ty * 4 + a];
            #pragma unroll
            for (int b = 0; b < 4; b++) rn[b] = Os[k * 65 + tx * 4 + b];
            #pragma unroll
            for (int a = 0; a < 4; a++)
                #pragma unroll
                for (int b = 0; b < 4; b++)
                    acc[a][b] += rc[a] * rn[b];
        }
        __syncthreads();
    }

    #pragma unroll
    for (int a = 0; a < 4; a++) {
        int c = c0 + ty * 4 + a;
        float bv = bias[c];
        float4 v = make_float4(acc[a][0] + bv, acc[a][1] + bv,
                               acc[a][2] + bv, acc[a][3] + bv);
        *(float4*)&out[((size_t)bb * Cn + c) * Nn + n0 + tx * 4] = v;
    }
}

// ---------------------------------------------------------------------------
extern "C" void kernel_launch(void* const* d_in, const int* in_sizes, int n_in,
                              void* d_out, int out_size) {
    const float* x      = (const float*)d_in[0];
    const float* ln_g   = (const float*)d_in[1];
    const float* ln_b   = (const float*)d_in[2];
    const float* w_qkv  = (const float*)d_in[3];
    const float* w_proj = (const float*)d_in[4];
    const float* b_proj = (const float*)d_in[5];
    float* out = (float*)d_out;

    ln_kernel<<<Bn * (Nn / 32), dim3(32, 8)>>>(x, ln_g, ln_b);
    qkv_kernel<<<dim3(12, (Bn * Nn) / 64), 256>>>(w_qkv);

    const int attn_smem = 64 * (QS + 2 * KTS + 2 * 64 + PS) * sizeof(float); // 200192 B
    cudaFuncSetAttribute(attn_kernel, cudaFuncAttributeMaxDynamicSharedMemorySize, attn_smem);
    attn_kernel<<<dim3(Nn / 256, Bn * NHn), 256, attn_smem>>>();

    proj_kernel<<<dim3(Nn / 64, Cn / 64, Bn), 256>>>(w_proj, b_proj, out);
}

// round 5
// speedup vs baseline: 1.9623x; 1.5791x over previous
#include <cuda_runtime.h>

#define Bn   4
#define Cn   256
#define Nn   4096
#define NHn  4
#define HDn  64

typedef unsigned long long u64;
typedef unsigned int u32;
typedef unsigned short u16;

// Scratch (device globals)
__device__ float g_tln[Bn * Nn * Cn];       // LN'd tokens [b][n][c]
__device__ float g_o[Bn * Nn * Cn];         // attention out [b][n][c]
// bf16 hi/lo split operands
__device__ u16 g_qh[Bn * NHn * Nn * HDn];   // [bh][n][d], pre-scaled
__device__ u16 g_ql[Bn * NHn * Nn * HDn];
__device__ u16 g_kh[Bn * NHn * Nn * HDn];   // [bh][n][d]
__device__ u16 g_kl[Bn * NHn * Nn * HDn];
__device__ u16 g_vh[Bn * NHn * HDn * Nn];   // [bh][dd][n] (d-major)
__device__ u16 g_vl[Bn * NHn * HDn * Nn];

// ============================ helpers ======================================
__device__ __forceinline__ u32 sptr(const void* p) {
    return (u32)__cvta_generic_to_shared(p);
}
__device__ __forceinline__ u32 packbf2(float lo, float hi) {
    u32 d;
    asm("cvt.rn.bf16x2.f32 %0, %1, %2;" : "=r"(d) : "f"(hi), "f"(lo));
    return d;
}
__device__ __forceinline__ float bflo(u32 v) { return __uint_as_float(v << 16); }
__device__ __forceinline__ float bfhi(u32 v) { return __uint_as_float(v & 0xffff0000u); }
__device__ __forceinline__ float ex2f(float x) {
    float r;
    asm("ex2.approx.ftz.f32 %0, %1;" : "=f"(r) : "f"(x));
    return r;
}
#define CPA16(dst, src) \
    asm volatile("cp.async.cg.shared.global [%0], [%1], 16;" :: "r"(dst), "l"(src))
#define CP_COMMIT  asm volatile("cp.async.commit_group;" ::: "memory")
#define CP_WAIT(n) asm volatile("cp.async.wait_group %0;" :: "n"(n) : "memory")

__device__ __forceinline__ void ldsm4(u32* r, u32 addr) {
    asm volatile("ldmatrix.sync.aligned.m8n8.x4.shared.b16 {%0,%1,%2,%3}, [%4];"
        : "=r"(r[0]), "=r"(r[1]), "=r"(r[2]), "=r"(r[3]) : "r"(addr));
}
__device__ __forceinline__ void mma16816(float* c, const u32* a, const u32* b) {
    asm volatile("mma.sync.aligned.m16n8k16.row.col.f32.bf16.bf16.f32 "
        "{%0,%1,%2,%3}, {%4,%5,%6,%7}, {%8,%9}, {%0,%1,%2,%3};"
        : "+f"(c[0]), "+f"(c[1]), "+f"(c[2]), "+f"(c[3])
        : "r"(a[0]), "r"(a[1]), "r"(a[2]), "r"(a[3]), "r"(b[0]), "r"(b[1]));
}

// ---------------------------------------------------------------------------
// Kernel 1: LayerNorm over C with NCHW -> [B,N,C] transpose.
// ---------------------------------------------------------------------------
__global__ void ln_kernel(const float* __restrict__ x,
                          const float* __restrict__ gamma,
                          const float* __restrict__ beta) {
    __shared__ float sm[256 * 33];
    __shared__ float red[2][8][32];
    __shared__ float sMean[32], sRstd[32];

    int blk = blockIdx.x;
    int bb  = blk >> 7;
    int n0  = (blk & 127) * 32;
    int tx  = threadIdx.x;
    int ty  = threadIdx.y;

    const float* xb = x + (size_t)bb * Cn * Nn;
    for (int c = ty; c < 256; c += 8)
        sm[c * 33 + tx] = xb[(size_t)c * Nn + n0 + tx];
    __syncthreads();

    float s = 0.f, s2 = 0.f;
    for (int c = ty; c < 256; c += 8) {
        float v = sm[c * 33 + tx];
        s += v; s2 += v * v;
    }
    red[0][ty][tx] = s;
    red[1][ty][tx] = s2;
    __syncthreads();

    if (ty == 0) {
        float a = 0.f, b2 = 0.f;
        #pragma unroll
        for (int i = 0; i < 8; i++) { a += red[0][i][tx]; b2 += red[1][i][tx]; }
        float mean = a * (1.f / 256.f);
        float var  = b2 * (1.f / 256.f) - mean * mean;
        sMean[tx] = mean;
        sRstd[tx] = rsqrtf(var + 1e-5f);
    }
    __syncthreads();

    int c = ty * 32 + tx;
    float gc = gamma[c], bc = beta[c];
    float* out = g_tln + ((size_t)bb * Nn + n0) * Cn;
    #pragma unroll 8
    for (int t = 0; t < 32; t++) {
        float v = (sm[c * 33 + t] - sMean[t]) * sRstd[t] * gc + bc;
        out[(size_t)t * Cn + c] = v;
    }
}

// ---------------------------------------------------------------------------
// Kernel 2: QKV GEMM -> bf16 hi/lo split outputs.
// ---------------------------------------------------------------------------
__global__ void qkv_kernel(const float* __restrict__ w) {
    __shared__ float As[16 * 65];
    __shared__ float Bs[16 * 64];

    int s  = blockIdx.x >> 2;
    int h  = blockIdx.x & 3;
    int n0 = blockIdx.x * 64;
    int m0 = blockIdx.y * 64;

    int tid = threadIdx.x;
    int tx = tid & 15, ty = tid >> 4;
    float acc[4][4] = {};

    const float* A = g_tln + (size_t)m0 * Cn;
    for (int k0 = 0; k0 < 256; k0 += 16) {
        #pragma unroll
        for (int l = 0; l < 4; l++) {
            int idx = tid + l * 256;
            int m = idx >> 4, k = idx & 15;
            As[k * 65 + m] = A[(size_t)m * Cn + k0 + k];
        }
        #pragma unroll
        for (int l = 0; l < 4; l++) {
            int idx = tid + l * 256;
            int k = idx >> 6, n = idx & 63;
            Bs[k * 64 + n] = w[(size_t)(k0 + k) * 768 + n0 + n];
        }
        __syncthreads();
        #pragma unroll
        for (int k = 0; k < 16; k++) {
            float ra[4], rb[4];
            #pragma unroll
            for (int a = 0; a < 4; a++) ra[a] = As[k * 65 + ty * 4 + a];
            #pragma unroll
            for (int b = 0; b < 4; b++) rb[b] = Bs[k * 64 + tx * 4 + b];
            #pragma unroll
            for (int a = 0; a < 4; a++)
                #pragma unroll
                for (int b = 0; b < 4; b++)
                    acc[a][b] += ra[a] * rb[b];
        }
        __syncthreads();
    }

    const int bb = m0 >> 12;
    const int nb = m0 & 4095;
    const size_t bhOff = ((size_t)bb * NHn + h);

    if (s == 2) {
        // V: [bh][dd][n], pairs packed along n (a, a+1)
        u16* vh = g_vh + bhOff * HDn * Nn;
        u16* vl = g_vl + bhOff * HDn * Nn;
        #pragma unroll
        for (int b = 0; b < 4; b++) {
            int dd = tx * 4 + b;
            #pragma unroll
            for (int a = 0; a < 4; a += 2) {
                int n = nb + ty * 4 + a;
                float x0 = acc[a][b], x1 = acc[a + 1][b];
                u32 hp = packbf2(x0, x1);
                u32 lp = packbf2(x0 - bflo(hp), x1 - bfhi(hp));
                *(u32*)&vh[(size_t)dd * Nn + n] = hp;
                *(u32*)&vl[(size_t)dd * Nn + n] = lp;
            }
        }
    } else {
        const float qs = (s == 0) ? 0.125f * 1.44269504088896340736f : 1.f;
        u16* dh = (s == 0 ? g_qh : g_kh) + (bhOff * Nn + nb) * HDn;
        u16* dl = (s == 0 ? g_ql : g_kl) + (bhOff * Nn + nb) * HDn;
        #pragma unroll
        for (int a = 0; a < 4; a++) {
            int n = ty * 4 + a;
            #pragma unroll
            for (int b = 0; b < 4; b += 2) {
                float x0 = acc[a][b] * qs, x1 = acc[a][b + 1] * qs;
                u32 hp = packbf2(x0, x1);
                u32 lp = packbf2(x0 - bflo(hp), x1 - bfhi(hp));
                *(u32*)&dh[(size_t)n * HDn + tx * 4 + b] = hp;
                *(u32*)&dl[(size_t)n * HDn + tx * 4 + b] = lp;
            }
        }
    }
}

// ---------------------------------------------------------------------------
// Kernel 3: mma.sync flash attention (bf16 3-pass split).
// Block: 128 q rows, 8 warps x 16 rows; key tiles of 128, double-buffered.
// ---------------------------------------------------------------------------
#define KRS 144   // K/Q smem row stride bytes (64 bf16 + pad)
#define VRS 272   // V smem row stride bytes (128 bf16 + pad)
#define SM_QH 0
#define SM_QL 18432
#define SM_KH 36864     // 2 x 18432
#define SM_KL 73728
#define SM_VH 110592    // 2 x 17408
#define SM_VL 145408
#define SM_TOT 180224
#define NT 32

__global__ __launch_bounds__(256, 1) void attn_mma_kernel() {
    extern __shared__ char sh[];
    const u32 base = sptr(sh);

    const int tid  = threadIdx.x;
    const int wid  = tid >> 5;
    const int lane = tid & 31;
    const int g    = lane >> 2;
    const int tg   = lane & 3;

    const int bh = blockIdx.y;
    const int q0 = blockIdx.x * 128;

    const char* Qh_g = (const char*)(g_qh + ((size_t)bh * Nn + q0) * HDn);
    const char* Ql_g = (const char*)(g_ql + ((size_t)bh * Nn + q0) * HDn);
    const char* Kh_g = (const char*)(g_kh + (size_t)bh * Nn * HDn);
    const char* Kl_g = (const char*)(g_kl + (size_t)bh * Nn * HDn);
    const char* Vh_g = (const char*)(g_vh + (size_t)bh * HDn * Nn);
    const char* Vl_g = (const char*)(g_vl + (size_t)bh * HDn * Nn);

    // cp.async thread mapping
    const int kRow = tid >> 1, kOff = (tid & 1) * 64;
    const u32 dK = (u32)kRow * KRS + kOff;
    const size_t sK = (size_t)kRow * 128 + kOff;       // + t*16384
    const int vRow = tid >> 2, vOff = (tid & 3) * 64;
    const u32 dV = (u32)vRow * VRS + vOff;
    const size_t sV = (size_t)vRow * (Nn * 2) + vOff;  // + t*256

    // prologue: Q tiles + K/V tile 0 (group 0), tile 1 (group 1)
    #pragma unroll
    for (int c = 0; c < 4; c++) {
        CPA16(base + SM_QH + dK + c * 16, Qh_g + sK + c * 16);
        CPA16(base + SM_QL + dK + c * 16, Ql_g + sK + c * 16);
    }
    #pragma unroll
    for (int c = 0; c < 4; c++) {
        CPA16(base + SM_KH + dK + c * 16, Kh_g + sK + c * 16);
        CPA16(base + SM_KL + dK + c * 16, Kl_g + sK + c * 16);
        CPA16(base + SM_VH + dV + c * 16, Vh_g + sV + c * 16);
        CPA16(base + SM_VL + dV + c * 16, Vl_g + sV + c * 16);
    }
    CP_COMMIT;
    #pragma unroll
    for (int c = 0; c < 4; c++) {
        CPA16(base + SM_KH + 18432 + dK + c * 16, Kh_g + 16384 + sK + c * 16);
        CPA16(base + SM_KL + 18432 + dK + c * 16, Kl_g + 16384 + sK + c * 16);
        CPA16(base + SM_VH + 17408 + dV + c * 16, Vh_g + 256 + sV + c * 16);
        CPA16(base + SM_VL + 17408 + dV + c * 16, Vl_g + 256 + sV + c * 16);
    }
    CP_COMMIT;

    // fragment address precompute
    const int r8 = lane & 7, mlo = (lane >> 3) & 1, mhi = (lane >> 4) & 1;
    const u32 aOff  = (u32)(wid * 16 + r8 + mlo * 8) * KRS + mhi * 16; // A (Q) rows
    const u32 bKoff = (u32)(r8 + mhi * 8) * KRS + mlo * 16;            // B (K)
    const u32 bVoff = (u32)r8 * VRS + (lane >> 3) * 16;                // B (V)

    CP_WAIT(1);
    __syncthreads();

    u32 qhf[4][4];
    #pragma unroll
    for (int kt = 0; kt < 4; kt++) ldsm4(qhf[kt], base + SM_QH + aOff + kt * 32);

    float s[64];
    float o[8][4];
    float mrow0 = -1e30f, mrow1 = -1e30f, lrow0 = 0.f, lrow1 = 0.f;
    #pragma unroll
    for (int vd = 0; vd < 8; vd++)
        #pragma unroll
        for (int e = 0; e < 4; e++) o[vd][e] = 0.f;

    for (int t = 0; t < NT; t++) {
        if (t > 0) {
            if (t == NT - 1) CP_WAIT(0); else CP_WAIT(1);
            __syncthreads();
        }
        const u32 cb = (t & 1);
        const u32 Kh = base + SM_KH + cb * 18432;
        const u32 Kl = base + SM_KL + cb * 18432;
        const u32 Vh = base + SM_VH + cb * 17408;
        const u32 Vl = base + SM_VL + cb * 17408;

        #pragma unroll
        for (int e = 0; e < 64; e++) s[e] = 0.f;

        // ---- QK^T: 3 passes ----
        #pragma unroll
        for (int kt = 0; kt < 4; kt++) {
            #pragma unroll
            for (int nt = 0; nt < 16; nt += 2) {
                u32 b[4];
                ldsm4(b, Kh + bKoff + nt * (8 * KRS) + kt * 32);
                mma16816(&s[nt * 4], qhf[kt], b);
                mma16816(&s[nt * 4 + 4], qhf[kt], b + 2);
            }
        }
        #pragma unroll
        for (int kt = 0; kt < 4; kt++) {
            #pragma unroll
            for (int nt = 0; nt < 16; nt += 2) {
                u32 b[4];
                ldsm4(b, Kl + bKoff + nt * (8 * KRS) + kt * 32);
                mma16816(&s[nt * 4], qhf[kt], b);
                mma16816(&s[nt * 4 + 4], qhf[kt], b + 2);
            }
        }
        #pragma unroll
        for (int kt = 0; kt < 4; kt++) {
            u32 qlf[4];
            ldsm4(qlf, base + SM_QL + aOff + kt * 32);
            #pragma unroll
            for (int nt = 0; nt < 16; nt += 2) {
                u32 b[4];
                ldsm4(b, Kh + bKoff + nt * (8 * KRS) + kt * 32);
                mma16816(&s[nt * 4], qlf, b);
                mma16816(&s[nt * 4 + 4], qlf, b + 2);
            }
        }

        // ---- online softmax (log2 domain; scale folded into Q) ----
        float mx0 = s[0], mx1 = s[2];
        #pragma unroll
        for (int nt = 0; nt < 16; nt++) {
            mx0 = fmaxf(mx0, fmaxf(s[nt * 4], s[nt * 4 + 1]));
            mx1 = fmaxf(mx1, fmaxf(s[nt * 4 + 2], s[nt * 4 + 3]));
        }
        mx0 = fmaxf(mx0, __shfl_xor_sync(0xffffffffu, mx0, 1));
        mx0 = fmaxf(mx0, __shfl_xor_sync(0xffffffffu, mx0, 2));
        mx1 = fmaxf(mx1, __shfl_xor_sync(0xffffffffu, mx1, 1));
        mx1 = fmaxf(mx1, __shfl_xor_sync(0xffffffffu, mx1, 2));

        float mn0 = fmaxf(mrow0, mx0), mn1 = fmaxf(mrow1, mx1);
        float c0 = ex2f(mrow0 - mn0), c1 = ex2f(mrow1 - mn1);
        mrow0 = mn0; mrow1 = mn1;

        float sum0 = 0.f, sum1 = 0.f;
        #pragma unroll
        for (int nt = 0; nt < 16; nt++) {
            float p0 = ex2f(s[nt * 4] - mn0);
            float p1 = ex2f(s[nt * 4 + 1] - mn0);
            float p2 = ex2f(s[nt * 4 + 2] - mn1);
            float p3 = ex2f(s[nt * 4 + 3] - mn1);
            s[nt * 4] = p0; s[nt * 4 + 1] = p1; s[nt * 4 + 2] = p2; s[nt * 4 + 3] = p3;
            sum0 += p0 + p1; sum1 += p2 + p3;
        }
        sum0 += __shfl_xor_sync(0xffffffffu, sum0, 1);
        sum0 += __shfl_xor_sync(0xffffffffu, sum0, 2);
        sum1 += __shfl_xor_sync(0xffffffffu, sum1, 1);
        sum1 += __shfl_xor_sync(0xffffffffu, sum1, 2);
        lrow0 = lrow0 * c0 + sum0;
        lrow1 = lrow1 * c1 + sum1;

        #pragma unroll
        for (int vd = 0; vd < 8; vd++) {
            o[vd][0] *= c0; o[vd][1] *= c0; o[vd][2] *= c1; o[vd][3] *= c1;
        }

        // pack P hi fragments (A-layout reuse)
        u32 ph[8][4];
        #pragma unroll
        for (int pk = 0; pk < 8; pk++) {
            ph[pk][0] = packbf2(s[pk * 8 + 0], s[pk * 8 + 1]);
            ph[pk][1] = packbf2(s[pk * 8 + 2], s[pk * 8 + 3]);
            ph[pk][2] = packbf2(s[pk * 8 + 4], s[pk * 8 + 5]);
            ph[pk][3] = packbf2(s[pk * 8 + 6], s[pk * 8 + 7]);
        }

        // ---- PV: 3 passes ----
        #pragma unroll
        for (int pkp = 0; pkp < 4; pkp++) {
            #pragma unroll
            for (int vd = 0; vd < 8; vd++) {
                u32 b[4];
                ldsm4(b, Vh + bVoff + vd * (8 * VRS) + pkp * 64);
                mma16816(o[vd], ph[2 * pkp], b);
                mma16816(o[vd], ph[2 * pkp + 1], b + 2);
            }
        }
        #pragma unroll
        for (int pkp = 0; pkp < 4; pkp++) {
            #pragma unroll
            for (int vd = 0; vd < 8; vd++) {
                u32 b[4];
                ldsm4(b, Vl + bVoff + vd * (8 * VRS) + pkp * 64);
                mma16816(o[vd], ph[2 * pkp], b);
                mma16816(o[vd], ph[2 * pkp + 1], b + 2);
            }
        }
        #pragma unroll
        for (int pkp = 0; pkp < 4; pkp++) {
            u32 pl[2][4];
            #pragma unroll
            for (int q = 0; q < 2; q++) {
                int pk = 2 * pkp + q;
                #pragma unroll
                for (int r = 0; r < 4; r++) {
                    float x0 = s[pk * 8 + 2 * r]     - bflo(ph[pk][r]);
                    float x1 = s[pk * 8 + 2 * r + 1] - bfhi(ph[pk][r]);
                    pl[q][r] = packbf2(x0, x1);
                }
            }
            #pragma unroll
            for (int vd = 0; vd < 8; vd++) {
                u32 b[4];
                ldsm4(b, Vh + bVoff + vd * (8 * VRS) + pkp * 64);
                mma16816(o[vd], pl[0], b);
                mma16816(o[vd], pl[1], b + 2);
            }
        }

        __syncthreads();   // everyone done reading buf cb before overwriting it
        if (t + 2 < NT) {
            const size_t kS = sK + (size_t)(t + 2) * 16384;
            const size_t vS = sV + (size_t)(t + 2) * 256;
            const u32 kD = dK + cb * 18432, vD = dV + cb * 17408;
            #pragma unroll
            for (int c = 0; c < 4; c++) {
                CPA16(base + SM_KH + kD + c * 16, Kh_g + kS + c * 16);
                CPA16(base + SM_KL + kD + c * 16, Kl_g + kS + c * 16);
                CPA16(base + SM_VH + vD + c * 16, Vh_g + vS + c * 16);
                CPA16(base + SM_VL + vD + c * 16, Vl_g + vS + c * 16);
            }
            CP_COMMIT;
        }
    }

    // epilogue: O rows wid*16+g, wid*16+8+g
    const int bb = bh >> 2, h = bh & 3;
    const float inv0 = 1.f / lrow0, inv1 = 1.f / lrow1;
    const int r0 = q0 + wid * 16 + g;
    float* O0 = g_o + ((size_t)bb * Nn + r0) * Cn + h * 64 + tg * 2;
    float* O1 = O0 + (size_t)8 * Cn;
    #pragma unroll
    for (int vd = 0; vd < 8; vd++) {
        *(float2*)&O0[vd * 8] = make_float2(o[vd][0] * inv0, o[vd][1] * inv0);
        *(float2*)&O1[vd * 8] = make_float2(o[vd][2] * inv1, o[vd][3] * inv1);
    }
}

// ---------------------------------------------------------------------------
// Kernel 4: output projection + bias -> transposed [B,C,N] output.
// ---------------------------------------------------------------------------
__global__ void proj_kernel(const float* __restrict__ w,
                            const float* __restrict__ bias,
                            float* __restrict__ out) {
    __shared__ float Ws[16 * 65];
    __shared__ float Os[16 * 65];

    int n0 = blockIdx.x * 64;
    int c0 = blockIdx.y * 64;
    int bb = blockIdx.z;

    int tid = threadIdx.x;
    int tx = tid & 15, ty = tid >> 4;
    float acc[4][4] = {};

    const float* A = g_o + (size_t)bb * Nn * Cn;
    for (int k0 = 0; k0 < 256; k0 += 16) {
        #pragma unroll
        for (int l = 0; l < 4; l++) {
            int idx = tid + l * 256;
            int r = idx >> 4, k = idx & 15;
            Ws[k * 65 + r] = w[(size_t)(c0 + r) * 256 + k0 + k];
            Os[k * 65 + r] = A[(size_t)(n0 + r) * 256 + k0 + k];
        }
        __syncthreads();
        #pragma unroll
        for (int k = 0; k < 16; k++) {
            float rc[4], rn[4];
            #pragma unroll
            for (int a = 0; a < 4; a++) rc[a] = Ws[k * 65 + ty * 4 + a];
            #pragma unroll
            for (int b = 0; b < 4; b++) rn[b] = Os[k * 65 + tx * 4 + b];
            #pragma unroll
            for (int a = 0; a < 4; a++)
                #pragma unroll
                for (int b = 0; b < 4; b++)
                    acc[a][b] += rc[a] * rn[b];
        }
        __syncthreads();
    }

    #pragma unroll
    for (int a = 0; a < 4; a++) {
        int c = c0 + ty * 4 + a;
        float bv = bias[c];
        float4 v = make_float4(acc[a][0] + bv, acc[a][1] + bv,
                               acc[a][2] + bv, acc[a][3] + bv);
        *(float4*)&out[((size_t)bb * Cn + c) * Nn + n0 + tx * 4] = v;
    }
}

// ---------------------------------------------------------------------------
extern "C" void kernel_launch(void* const* d_in, const int* in_sizes, int n_in,
                              void* d_out, int out_size) {
    const float* x      = (const float*)d_in[0];
    const float* ln_g   = (const float*)d_in[1];
    const float* ln_b   = (const float*)d_in[2];
    const float* w_qkv  = (const float*)d_in[3];
    const float* w_proj = (const float*)d_in[4];
    const float* b_proj = (const float*)d_in[5];
    float* out = (float*)d_out;

    ln_kernel<<<Bn * (Nn / 32), dim3(32, 8)>>>(x, ln_g, ln_b);
    qkv_kernel<<<dim3(12, (Bn * Nn) / 64), 256>>>(w_qkv);

    cudaFuncSetAttribute(attn_mma_kernel, cudaFuncAttributeMaxDynamicSharedMemorySize, SM_TOT);
    attn_mma_kernel<<<dim3(Nn / 128, Bn * NHn), 256, SM_TOT>>>();

    proj_kernel<<<dim3(Nn / 64, Cn / 64, Bn), 256>>>(w_proj, b_proj, out);
}

// round 7
// speedup vs baseline: 2.1557x; 1.0985x over previous
#include <cuda_runtime.h>

#define Bn   4
#define Cn   256
#define Nn   4096
#define NHn  4
#define HDn  64

typedef unsigned long long u64;
typedef unsigned int u32;
typedef unsigned short u16;

// Scratch (device globals)
__device__ float g_o[Bn * Nn * Cn];         // attention out [b][n][c]
// bf16 hi/lo split operands
__device__ u16 g_tlh[Bn * Nn * Cn];         // LN'd tokens hi [b*n][c]
__device__ u16 g_tll[Bn * Nn * Cn];
__device__ u16 g_wth[768 * 256];            // w_qkv^T hi [ncol][k]
__device__ u16 g_wtl[768 * 256];
__device__ u16 g_qh[Bn * NHn * Nn * HDn];   // [bh][n][d], pre-scaled
__device__ u16 g_ql[Bn * NHn * Nn * HDn];
__device__ u16 g_kh[Bn * NHn * Nn * HDn];   // [bh][n][d]
__device__ u16 g_kl[Bn * NHn * Nn * HDn];
__device__ u16 g_vh[Bn * NHn * HDn * Nn];   // [bh][dd][n] (d-major)
__device__ u16 g_vl[Bn * NHn * HDn * Nn];

// ============================ helpers ======================================
__device__ __forceinline__ u32 sptr(const void* p) {
    return (u32)__cvta_generic_to_shared(p);
}
__device__ __forceinline__ u32 packbf2(float lo, float hi) {
    u32 d;
    asm("cvt.rn.bf16x2.f32 %0, %1, %2;" : "=r"(d) : "f"(hi), "f"(lo));
    return d;
}
__device__ __forceinline__ float bflo(u32 v) { return __uint_as_float(v << 16); }
__device__ __forceinline__ float bfhi(u32 v) { return __uint_as_float(v & 0xffff0000u); }
__device__ __forceinline__ float ex2f(float x) {
    float r;
    asm("ex2.approx.ftz.f32 %0, %1;" : "=f"(r) : "f"(x));
    return r;
}
#define CPA16(dst, src) \
    asm volatile("cp.async.cg.shared.global [%0], [%1], 16;" :: "r"(dst), "l"(src))
#define CP_COMMIT  asm volatile("cp.async.commit_group;" ::: "memory")
#define CP_WAIT(n) asm volatile("cp.async.wait_group %0;" :: "n"(n) : "memory")

__device__ __forceinline__ void ldsm4(u32* r, u32 addr) {
    asm volatile("ldmatrix.sync.aligned.m8n8.x4.shared.b16 {%0,%1,%2,%3}, [%4];"
        : "=r"(r[0]), "=r"(r[1]), "=r"(r[2]), "=r"(r[3]) : "r"(addr));
}
__device__ __forceinline__ void mma16816(float* c, const u32* a, const u32* b) {
    asm volatile("mma.sync.aligned.m16n8k16.row.col.f32.bf16.bf16.f32 "
        "{%0,%1,%2,%3}, {%4,%5,%6,%7}, {%8,%9}, {%0,%1,%2,%3};"
        : "+f"(c[0]), "+f"(c[1]), "+f"(c[2]), "+f"(c[3])
        : "r"(a[0]), "r"(a[1]), "r"(a[2]), "r"(a[3]), "r"(b[0]), "r"(b[1]));
}

// ---------------------------------------------------------------------------
// Kernel 1: LayerNorm over C, NCHW -> [B,N,C], emits bf16 hi/lo split.
// ---------------------------------------------------------------------------
__global__ void ln_kernel(const float* __restrict__ x,
                          const float* __restrict__ gamma,
                          const float* __restrict__ beta) {
    __shared__ float sm[256 * 33];
    __shared__ float red[2][8][32];
    __shared__ float sMean[32], sRstd[32];

    int blk = blockIdx.x;
    int bb  = blk >> 7;
    int n0  = (blk & 127) * 32;
    int tx  = threadIdx.x;
    int ty  = threadIdx.y;

    const float* xb = x + (size_t)bb * Cn * Nn;
    for (int c = ty; c < 256; c += 8)
        sm[c * 33 + tx] = xb[(size_t)c * Nn + n0 + tx];
    __syncthreads();

    float s = 0.f, s2 = 0.f;
    for (int c = ty; c < 256; c += 8) {
        float v = sm[c * 33 + tx];
        s += v; s2 += v * v;
    }
    red[0][ty][tx] = s;
    red[1][ty][tx] = s2;
    __syncthreads();

    if (ty == 0) {
        float a = 0.f, b2 = 0.f;
        #pragma unroll
        for (int i = 0; i < 8; i++) { a += red[0][i][tx]; b2 += red[1][i][tx]; }
        float mean = a * (1.f / 256.f);
        float var  = b2 * (1.f / 256.f) - mean * mean;
        sMean[tx] = mean;
        sRstd[tx] = rsqrtf(var + 1e-5f);
    }
    __syncthreads();

    int c = ty * 32 + tx;
    float gc = gamma[c], bc = beta[c];
    u16* outh = g_tlh + ((size_t)bb * Nn + n0) * Cn;
    u16* outl = g_tll + ((size_t)bb * Nn + n0) * Cn;
    #pragma unroll 8
    for (int t = 0; t < 32; t++) {
        float v = (sm[c * 33 + t] - sMean[t]) * sRstd[t] * gc + bc;
        u32 hp = packbf2(v, v);
        float r = v - bflo(hp);
        u32 lp = packbf2(r, r);
        outh[(size_t)t * Cn + c] = (u16)hp;
        outl[(size_t)t * Cn + c] = (u16)lp;
    }
}

// ---------------------------------------------------------------------------
// Kernel 1b: transpose + split w_qkv [256][768] -> wT hi/lo [768][256].
// ---------------------------------------------------------------------------
__global__ void wsplit_kernel(const float* __restrict__ w) {
    __shared__ float tile[32][33];
    int bx = blockIdx.x;   // ncol tile (24)
    int by = blockIdx.y;   // k tile (8)
    int tx = threadIdx.x, ty = threadIdx.y;   // (32, 8)
    #pragma unroll
    for (int i = 0; i < 4; i++)
        tile[ty + i * 8][tx] = w[(size_t)(by * 32 + ty + i * 8) * 768 + bx * 32 + tx];
    __syncthreads();
    #pragma unroll
    for (int i = 0; i < 4; i++) {
        float v = tile[tx][ty + i * 8];
        u32 hp = packbf2(v, v);
        float r = v - bflo(hp);
        u32 lp = packbf2(r, r);
        size_t o = (size_t)(bx * 32 + ty + i * 8) * 256 + by * 32 + tx;
        g_wth[o] = (u16)hp;
        g_wtl[o] = (u16)lp;
    }
}

// ---------------------------------------------------------------------------
// Kernel 2: QKV GEMM on tensor cores (bf16 3-pass split).
// Block: 128 tokens x 64 weight-cols (= one (s,h)); K=256 in 4 chunks,
// cp.async double-buffered. 8 warps x 16 rows.
// ---------------------------------------------------------------------------
#define QKRS 144
#define QA_H0 0
#define QA_H1 18432
#define QA_L0 36864
#define QA_L1 55296
#define QB_H0 73728
#define QB_H1 82944
#define QB_L0 92160
#define QB_L1 101376
#define QSM_TOT 110592

__global__ __launch_bounds__(256, 1) void qkv_mma_kernel() {
    extern __shared__ char sh[];
    const u32 base = sptr(sh);
    const int tid = threadIdx.x, wid = tid >> 5, lane = tid & 31;
    const int g = lane >> 2, tg = lane & 3;

    const int m0 = blockIdx.x * 128;      // token tile
    const int n0 = blockIdx.y * 64;       // weight col tile
    const int s  = n0 >> 8;
    const int h  = (n0 >> 6) & 3;
    const int bb = m0 >> 12;
    const int ntok0 = m0 & 4095;
    const size_t bhOff = (size_t)bb * NHn + h;

    // cp.async mappings
    const int aRow = tid >> 1, aOff = (tid & 1) * 64;
    const u32 dA = (u32)aRow * QKRS + aOff;
    const int bRow = tid >> 2, bOff = (tid & 3) * 32;
    const u32 dB = (u32)bRow * QKRS + bOff;

    const char* Ah_g = (const char*)(g_tlh + (size_t)m0 * Cn);
    const char* Al_g = (const char*)(g_tll + (size_t)m0 * Cn);
    const char* Bh_g = (const char*)g_wth;
    const char* Bl_g = (const char*)g_wtl;

    // prefetch chunks 0 and 1
    #pragma unroll
    for (int pc = 0; pc < 2; pc++) {
        const int k0 = pc * 64;
        const u32 ah = base + (pc ? QA_H1 : QA_H0) + dA;
        const u32 al = base + (pc ? QA_L1 : QA_L0) + dA;
        const u32 bh = base + (pc ? QB_H1 : QB_H0) + dB;
        const u32 bl = base + (pc ? QB_L1 : QB_L0) + dB;
        const size_t sa = (size_t)aRow * 512 + k0 * 2 + aOff;
        const size_t sb = (size_t)(n0 + bRow) * 512 + k0 * 2 + bOff;
        #pragma unroll
        for (int c = 0; c < 4; c++) {
            CPA16(ah + c * 16, Ah_g + sa + c * 16);
            CPA16(al + c * 16, Al_g + sa + c * 16);
        }
        #pragma unroll
        for (int c = 0; c < 2; c++) {
            CPA16(bh + c * 16, Bh_g + sb + c * 16);
            CPA16(bl + c * 16, Bl_g + sb + c * 16);
        }
        CP_COMMIT;
    }

    const int r8 = lane & 7, mlo = (lane >> 3) & 1, mhi = (lane >> 4) & 1;
    const u32 aFrag = (u32)(wid * 16 + r8 + mlo * 8) * QKRS + mhi * 16;
    const u32 bFrag = (u32)(r8 + mhi * 8) * QKRS + mlo * 16;

    float sAcc[32];
    #pragma unroll
    for (int e = 0; e < 32; e++) sAcc[e] = 0.f;

    for (int ck = 0; ck < 4; ck++) {
        if (ck < 3) CP_WAIT(1); else CP_WAIT(0);
        __syncthreads();
        const int buf = ck & 1;
        const u32 AH = base + (buf ? QA_H1 : QA_H0);
        const u32 AL = base + (buf ? QA_L1 : QA_L0);
        const u32 BH = base + (buf ? QB_H1 : QB_H0);
        const u32 BL = base + (buf ? QB_L1 : QB_L0);

        #pragma unroll
        for (int kt = 0; kt < 4; kt++) {
            u32 ah[4], al[4];
            ldsm4(ah, AH + aFrag + kt * 32);
            ldsm4(al, AL + aFrag + kt * 32);
            #pragma unroll
            for (int ntp = 0; ntp < 4; ntp++) {
                u32 bh[4], bl[4];
                ldsm4(bh, BH + bFrag + ntp * (16 * QKRS) + kt * 32);
                mma16816(&sAcc[ntp * 8], ah, bh);
                mma16816(&sAcc[ntp * 8 + 4], ah, bh + 2);
                ldsm4(bl, BL + bFrag + ntp * (16 * QKRS) + kt * 32);
                mma16816(&sAcc[ntp * 8], ah, bl);
                mma16816(&sAcc[ntp * 8 + 4], ah, bl + 2);
                mma16816(&sAcc[ntp * 8], al, bh);
                mma16816(&sAcc[ntp * 8 + 4], al, bh + 2);
            }
        }

        __syncthreads();
        if (ck + 2 < 4) {
            const int k0 = (ck + 2) * 64;
            const u32 ah = base + (buf ? QA_H1 : QA_H0) + dA;
            const u32 al = base + (buf ? QA_L1 : QA_L0) + dA;
            const u32 bh = base + (buf ? QB_H1 : QB_H0) + dB;
            const u32 bl = base + (buf ? QB_L1 : QB_L0) + dB;
            const size_t sa = (size_t)aRow * 512 + k0 * 2 + aOff;
            const size_t sb = (size_t)(n0 + bRow) * 512 + k0 * 2 + bOff;
            #pragma unroll
            for (int c = 0; c < 4; c++) {
                CPA16(ah + c * 16, Ah_g + sa + c * 16);
                CPA16(al + c * 16, Al_g + sa + c * 16);
            }
            #pragma unroll
            for (int c = 0; c < 2; c++) {
                CPA16(bh + c * 16, Bh_g + sb + c * 16);
                CPA16(bl + c * 16, Bl_g + sb + c * 16);
            }
            CP_COMMIT;
        }
    }

    if (s < 2) {
        // q / k: [bh][n][d], q pre-scaled
        const float qs = (s == 0) ? 0.125f * 1.44269504088896340736f : 1.f;
        u16* dh = (s == 0 ? g_qh : g_kh) + (bhOff * Nn + ntok0 + wid * 16 + g) * HDn;
        u16* dl = (s == 0 ? g_ql : g_kl) + (bhOff * Nn + ntok0 + wid * 16 + g) * HDn;
        #pragma unroll
        for (int ntp = 0; ntp < 4; ntp++) {
            #pragma unroll
            for (int q = 0; q < 2; q++) {
                int d = ntp * 16 + q * 8 + tg * 2;
                float x0 = sAcc[ntp * 8 + q * 4]     * qs;
                float x1 = sAcc[ntp * 8 + q * 4 + 1] * qs;
                u32 hp = packbf2(x0, x1);
                u32 lp = packbf2(x0 - bflo(hp), x1 - bfhi(hp));
                *(u32*)&dh[d] = hp;
                *(u32*)&dl[d] = lp;
                x0 = sAcc[ntp * 8 + q * 4 + 2] * qs;   // FIX: rows g+8 were unscaled
                x1 = sAcc[ntp * 8 + q * 4 + 3] * qs;
                hp = packbf2(x0, x1);
                lp = packbf2(x0 - bflo(hp), x1 - bfhi(hp));
                *(u32*)&dh[8 * HDn + d] = hp;
                *(u32*)&dl[8 * HDn + d] = lp;
            }
        }
    } else {
        // v: transpose to [bh][dd][n] via smem (stride 132 -> conflict-free)
        float* vt = (float*)sh;
        const int nl = wid * 16 + g;
        #pragma unroll
        for (int ntp = 0; ntp < 4; ntp++) {
            #pragma unroll
            for (int q = 0; q < 2; q++) {
                int dd = ntp * 16 + q * 8 + tg * 2;
                vt[(size_t)dd * 132 + nl]           = sAcc[ntp * 8 + q * 4];
                vt[(size_t)(dd + 1) * 132 + nl]     = sAcc[ntp * 8 + q * 4 + 1];
                vt[(size_t)dd * 132 + nl + 8]       = sAcc[ntp * 8 + q * 4 + 2];
                vt[(size_t)(dd + 1) * 132 + nl + 8] = sAcc[ntp * 8 + q * 4 + 3];
            }
        }
        __syncthreads();
        u16* vh = g_vh + bhOff * HDn * Nn;
        u16* vl = g_vl + bhOff * HDn * Nn;
        #pragma unroll
        for (int e = 0; e < 16; e++) {
            int idx = e * 256 + tid;
            int dd = idx >> 6, np = idx & 63;
            float x0 = vt[(size_t)dd * 132 + np * 2];
            float x1 = vt[(size_t)dd * 132 + np * 2 + 1];
            u32 hp = packbf2(x0, x1);
            u32 lp = packbf2(x0 - bflo(hp), x1 - bfhi(hp));
            *(u32*)&vh[(size_t)dd * Nn + ntok0 + np * 2] = hp;
            *(u32*)&vl[(size_t)dd * Nn + ntok0 + np * 2] = lp;
        }
    }
}

// ---------------------------------------------------------------------------
// Kernel 3: mma.sync flash attention (bf16 3-pass split).
// ---------------------------------------------------------------------------
#define KRS 144
#define VRS 272
#define SM_QH 0
#define SM_QL 18432
#define SM_KH 36864
#define SM_KL 73728
#define SM_VH 110592
#define SM_VL 145408
#define SM_TOT 180224
#define NT 32

__global__ __launch_bounds__(256, 1) void attn_mma_kernel() {
    extern __shared__ char sh[];
    const u32 base = sptr(sh);

    const int tid  = threadIdx.x;
    const int wid  = tid >> 5;
    const int lane = tid & 31;
    const int g    = lane >> 2;
    const int tg   = lane & 3;

    const int bh = blockIdx.y;
    const int q0 = blockIdx.x * 128;

    const char* Qh_g = (const char*)(g_qh + ((size_t)bh * Nn + q0) * HDn);
    const char* Ql_g = (const char*)(g_ql + ((size_t)bh * Nn + q0) * HDn);
    const char* Kh_g = (const char*)(g_kh + (size_t)bh * Nn * HDn);
    const char* Kl_g = (const char*)(g_kl + (size_t)bh * Nn * HDn);
    const char* Vh_g = (const char*)(g_vh + (size_t)bh * HDn * Nn);
    const char* Vl_g = (const char*)(g_vl + (size_t)bh * HDn * Nn);

    const int kRow = tid >> 1, kOff = (tid & 1) * 64;
    const u32 dK = (u32)kRow * KRS + kOff;
    const size_t sK = (size_t)kRow * 128 + kOff;
    const int vRow = tid >> 2, vOff = (tid & 3) * 64;
    const u32 dV = (u32)vRow * VRS + vOff;
    const size_t sV = (size_t)vRow * (Nn * 2) + vOff;

    #pragma unroll
    for (int c = 0; c < 4; c++) {
        CPA16(base + SM_QH + dK + c * 16, Qh_g + sK + c * 16);
        CPA16(base + SM_QL + dK + c * 16, Ql_g + sK + c * 16);
    }
    #pragma unroll
    for (int c = 0; c < 4; c++) {
        CPA16(base + SM_KH + dK + c * 16, Kh_g + sK + c * 16);
        CPA16(base + SM_KL + dK + c * 16, Kl_g + sK + c * 16);
        CPA16(base + SM_VH + dV + c * 16, Vh_g + sV + c * 16);
        CPA16(base + SM_VL + dV + c * 16, Vl_g + sV + c * 16);
    }
    CP_COMMIT;
    #pragma unroll
    for (int c = 0; c < 4; c++) {
        CPA16(base + SM_KH + 18432 + dK + c * 16, Kh_g + 16384 + sK + c * 16);
        CPA16(base + SM_KL + 18432 + dK + c * 16, Kl_g + 16384 + sK + c * 16);
        CPA16(base + SM_VH + 17408 + dV + c * 16, Vh_g + 256 + sV + c * 16);
        CPA16(base + SM_VL + 17408 + dV + c * 16, Vl_g + 256 + sV + c * 16);
    }
    CP_COMMIT;

    const int r8 = lane & 7, mlo = (lane >> 3) & 1, mhi = (lane >> 4) & 1;
    const u32 aOff  = (u32)(wid * 16 + r8 + mlo * 8) * KRS + mhi * 16;
    const u32 bKoff = (u32)(r8 + mhi * 8) * KRS + mlo * 16;
    const u32 bVoff = (u32)r8 * VRS + (lane >> 3) * 16;

    CP_WAIT(1);
    __syncthreads();

    u32 qhf[4][4];
    #pragma unroll
    for (int kt = 0; kt < 4; kt++) ldsm4(qhf[kt], base + SM_QH + aOff + kt * 32);

    float s[64];
    float o[8][4];
    float mrow0 = -1e30f, mrow1 = -1e30f, lrow0 = 0.f, lrow1 = 0.f;
    #pragma unroll
    for (int vd = 0; vd < 8; vd++)
        #pragma unroll
        for (int e = 0; e < 4; e++) o[vd][e] = 0.f;

    for (int t = 0; t < NT; t++) {
        if (t > 0) {
            if (t == NT - 1) CP_WAIT(0); else CP_WAIT(1);
            __syncthreads();
        }
        const u32 cb = (t & 1);
        const u32 Kh = base + SM_KH + cb * 18432;
        const u32 Kl = base + SM_KL + cb * 18432;
        const u32 Vh = base + SM_VH + cb * 17408;
        const u32 Vl = base + SM_VL + cb * 17408;

        #pragma unroll
        for (int e = 0; e < 64; e++) s[e] = 0.f;

        #pragma unroll
        for (int kt = 0; kt < 4; kt++) {
            #pragma unroll
            for (int nt = 0; nt < 16; nt += 2) {
                u32 b[4];
                ldsm4(b, Kh + bKoff + nt * (8 * KRS) + kt * 32);
                mma16816(&s[nt * 4], qhf[kt], b);
                mma16816(&s[nt * 4 + 4], qhf[kt], b + 2);
            }
        }
        #pragma unroll
        for (int kt = 0; kt < 4; kt++) {
            #pragma unroll
            for (int nt = 0; nt < 16; nt += 2) {
                u32 b[4];
                ldsm4(b, Kl + bKoff + nt * (8 * KRS) + kt * 32);
                mma16816(&s[nt * 4], qhf[kt], b);
                mma16816(&s[nt * 4 + 4], qhf[kt], b + 2);
            }
        }
        #pragma unroll
        for (int kt = 0; kt < 4; kt++) {
            u32 qlf[4];
            ldsm4(qlf, base + SM_QL + aOff + kt * 32);
            #pragma unroll
            for (int nt = 0; nt < 16; nt += 2) {
                u32 b[4];
                ldsm4(b, Kh + bKoff + nt * (8 * KRS) + kt * 32);
                mma16816(&s[nt * 4], qlf, b);
                mma16816(&s[nt * 4 + 4], qlf, b + 2);
            }
        }

        float mx0 = s[0], mx1 = s[2];
        #pragma unroll
        for (int nt = 0; nt < 16; nt++) {
            mx0 = fmaxf(mx0, fmaxf(s[nt * 4], s[nt * 4 + 1]));
            mx1 = fmaxf(mx1, fmaxf(s[nt * 4 + 2], s[nt * 4 + 3]));
        }
        mx0 = fmaxf(mx0, __shfl_xor_sync(0xffffffffu, mx0, 1));
        mx0 = fmaxf(mx0, __shfl_xor_sync(0xffffffffu, mx0, 2));
        mx1 = fmaxf(mx1, __shfl_xor_sync(0xffffffffu, mx1, 1));
        mx1 = fmaxf(mx1, __shfl_xor_sync(0xffffffffu, mx1, 2));

        float mn0 = fmaxf(mrow0, mx0), mn1 = fmaxf(mrow1, mx1);
        float c0 = ex2f(mrow0 - mn0), c1 = ex2f(mrow1 - mn1);
        mrow0 = mn0; mrow1 = mn1;

        float sum0 = 0.f, sum1 = 0.f;
        #pragma unroll
        for (int nt = 0; nt < 16; nt++) {
            float p0 = ex2f(s[nt * 4] - mn0);
            float p1 = ex2f(s[nt * 4 + 1] - mn0);
            float p2 = ex2f(s[nt * 4 + 2] - mn1);
            float p3 = ex2f(s[nt * 4 + 3] - mn1);
            s[nt * 4] = p0; s[nt * 4 + 1] = p1; s[nt * 4 + 2] = p2; s[nt * 4 + 3] = p3;
            sum0 += p0 + p1; sum1 += p2 + p3;
        }
        sum0 += __shfl_xor_sync(0xffffffffu, sum0, 1);
        sum0 += __shfl_xor_sync(0xffffffffu, sum0, 2);
        sum1 += __shfl_xor_sync(0xffffffffu, sum1, 1);
        sum1 += __shfl_xor_sync(0xffffffffu, sum1, 2);
        lrow0 = lrow0 * c0 + sum0;
        lrow1 = lrow1 * c1 + sum1;

        #pragma unroll
        for (int vd = 0; vd < 8; vd++) {
            o[vd][0] *= c0; o[vd][1] *= c0; o[vd][2] *= c1; o[vd][3] *= c1;
        }

        u32 ph[8][4];
        #pragma unroll
        for (int pk = 0; pk < 8; pk++) {
            ph[pk][0] = packbf2(s[pk * 8 + 0], s[pk * 8 + 1]);
            ph[pk][1] = packbf2(s[pk * 8 + 2], s[pk * 8 + 3]);
            ph[pk][2] = packbf2(s[pk * 8 + 4], s[pk * 8 + 5]);
            ph[pk][3] = packbf2(s[pk * 8 + 6], s[pk * 8 + 7]);
        }

        #pragma unroll
        for (int pkp = 0; pkp < 4; pkp++) {
            #pragma unroll
            for (int vd = 0; vd < 8; vd++) {
                u32 b[4];
                ldsm4(b, Vh + bVoff + vd * (8 * VRS) + pkp * 64);
                mma16816(o[vd], ph[2 * pkp], b);
                mma16816(o[vd], ph[2 * pkp + 1], b + 2);
            }
        }
        #pragma unroll
        for (int pkp = 0; pkp < 4; pkp++) {
            #pragma unroll
            for (int vd = 0; vd < 8; vd++) {
                u32 b[4];
                ldsm4(b, Vl + bVoff + vd * (8 * VRS) + pkp * 64);
                mma16816(o[vd], ph[2 * pkp], b);
                mma16816(o[vd], ph[2 * pkp + 1], b + 2);
            }
        }
        #pragma unroll
        for (int pkp = 0; pkp < 4; pkp++) {
            u32 pl[2][4];
            #pragma unroll
            for (int q = 0; q < 2; q++) {
                int pk = 2 * pkp + q;
                #pragma unroll
                for (int r = 0; r < 4; r++) {
                    float x0 = s[pk * 8 + 2 * r]     - bflo(ph[pk][r]);
                    float x1 = s[pk * 8 + 2 * r + 1] - bfhi(ph[pk][r]);
                    pl[q][r] = packbf2(x0, x1);
                }
            }
            #pragma unroll
            for (int vd = 0; vd < 8; vd++) {
                u32 b[4];
                ldsm4(b, Vh + bVoff + vd * (8 * VRS) + pkp * 64);
                mma16816(o[vd], pl[0], b);
                mma16816(o[vd], pl[1], b + 2);
            }
        }

        __syncthreads();
        if (t + 2 < NT) {
            const size_t kS = sK + (size_t)(t + 2) * 16384;
            const size_t vS = sV + (size_t)(t + 2) * 256;
            const u32 kD = dK + cb * 18432, vD = dV + cb * 17408;
            #pragma unroll
            for (int c = 0; c < 4; c++) {
                CPA16(base + SM_KH + kD + c * 16, Kh_g + kS + c * 16);
                CPA16(base + SM_KL + kD + c * 16, Kl_g + kS + c * 16);
                CPA16(base + SM_VH + vD + c * 16, Vh_g + vS + c * 16);
                CPA16(base + SM_VL + vD + c * 16, Vl_g + vS + c * 16);
            }
            CP_COMMIT;
        }
    }

    const int bb = bh >> 2, h = bh & 3;
    const float inv0 = 1.f / lrow0, inv1 = 1.f / lrow1;
    const int r0 = q0 + wid * 16 + g;
    float* O0 = g_o + ((size_t)bb * Nn + r0) * Cn + h * 64 + tg * 2;
    float* O1 = O0 + (size_t)8 * Cn;
    #pragma unroll
    for (int vd = 0; vd < 8; vd++) {
        *(float2*)&O0[vd * 8] = make_float2(o[vd][0] * inv0, o[vd][1] * inv0);
        *(float2*)&O1[vd * 8] = make_float2(o[vd][2] * inv1, o[vd][3] * inv1);
    }
}

// ---------------------------------------------------------------------------
// Kernel 4: output projection + bias -> transposed [B,C,N] output.
// ---------------------------------------------------------------------------
__global__ void proj_kernel(const float* __restrict__ w,
                            const float* __restrict__ bias,
                            float* __restrict__ out) {
    __shared__ float Ws[16 * 65];
    __shared__ float Os[16 * 65];

    int n0 = blockIdx.x * 64;
    int c0 = blockIdx.y * 64;
    int bb = blockIdx.z;

    int tid = threadIdx.x;
    int tx = tid & 15, ty = tid >> 4;
    float acc[4][4] = {};

    const float* A = g_o + (size_t)bb * Nn * Cn;
    for (int k0 = 0; k0 < 256; k0 += 16) {
        #pragma unroll
        for (int l = 0; l < 4; l++) {
            int idx = tid + l * 256;
            int r = idx >> 4, k = idx & 15;
            Ws[k * 65 + r] = w[(size_t)(c0 + r) * 256 + k0 + k];
            Os[k * 65 + r] = A[(size_t)(n0 + r) * 256 + k0 + k];
        }
        __syncthreads();
        #pragma unroll
        for (int k = 0; k < 16; k++) {
            float rc[4], rn[4];
            #pragma unroll
            for (int a = 0; a < 4; a++) rc[a] = Ws[k * 65 + ty * 4 + a];
            #pragma unroll
            for (int b = 0; b < 4; b++) rn[b] = Os[k * 65 + tx * 4 + b];
            #pragma unroll
            for (int a = 0; a < 4; a++)
                #pragma unroll
                for (int b = 0; b < 4; b++)
                    acc[a][b] += rc[a] * rn[b];
        }
        __syncthreads();
    }

    #pragma unroll
    for (int a = 0; a < 4; a++) {
        int c = c0 + ty * 4 + a;
        float bv = bias[c];
        float4 v = make_float4(acc[a][0] + bv, acc[a][1] + bv,
                               acc[a][2] + bv, acc[a][3] + bv);
        *(float4*)&out[((size_t)bb * Cn + c) * Nn + n0 + tx * 4] = v;
    }
}

// ---------------------------------------------------------------------------
extern "C" void kernel_launch(void* const* d_in, const int* in_sizes, int n_in,
                              void* d_out, int out_size) {
    const float* x      = (const float*)d_in[0];
    const float* ln_g   = (const float*)d_in[1];
    const float* ln_b   = (const float*)d_in[2];
    const float* w_qkv  = (const float*)d_in[3];
    const float* w_proj = (const float*)d_in[4];
    const float* b_proj = (const float*)d_in[5];
    float* out = (float*)d_out;

    ln_kernel<<<Bn * (Nn / 32), dim3(32, 8)>>>(x, ln_g, ln_b);
    wsplit_kernel<<<dim3(24, 8), dim3(32, 8)>>>(w_qkv);

    cudaFuncSetAttribute(qkv_mma_kernel, cudaFuncAttributeMaxDynamicSharedMemorySize, QSM_TOT);
    qkv_mma_kernel<<<dim3(128, 12), 256, QSM_TOT>>>();

    cudaFuncSetAttribute(attn_mma_kernel, cudaFuncAttributeMaxDynamicSharedMemorySize, SM_TOT);
    attn_mma_kernel<<<dim3(Nn / 128, Bn * NHn), 256, SM_TOT>>>();

    proj_kernel<<<dim3(Nn / 64, Cn / 64, Bn), 256>>>(w_proj, b_proj, out);
}